// round 8
// baseline (speedup 1.0000x reference)
#include <cuda_runtime.h>
#include <cstdint>

// Shapes: B=4, H=W=64 -> N=4096 tokens per batch, C=256, FQ=32.
#define BATCH 4
#define NTOK 4096
#define CDIM 256
#define FQ 32
#define ROWS_TOTAL (BATCH * NTOK)   // 16384

// Scratch (no allocations allowed -> __device__ globals)
__device__ float g_q[ROWS_TOTAL * FQ];
__device__ float g_k[ROWS_TOTAL * FQ];
__device__ float g_v[ROWS_TOTAL * CDIM];
__device__ float g_att[ROWS_TOTAL * CDIM];

__device__ __forceinline__ float relu(float v) { return v > 0.0f ? v : 0.0f; }

// ---------------------------------------------------------------------------
// Kernel 1: fused QKV projection.
// x [16384, 256] -> q [16384,32], k [16384,32], v [16384,256], all ReLU'd.
// grid: (256 row tiles, 5 col tiles). col tile 0 = q(0..31)|k(32..63),
// col tiles 1..4 = v columns (ct-1)*64 .. +63.
// Block 256 threads, 64x64 output tile, 4x4 micro-tile per thread.
// ---------------------------------------------------------------------------
__global__ __launch_bounds__(256) void qkv_kernel(
    const float* __restrict__ x,
    const float* __restrict__ Wq, const float* __restrict__ bq,
    const float* __restrict__ Wk, const float* __restrict__ bk,
    const float* __restrict__ Wv, const float* __restrict__ bv)
{
    __shared__ float Xt[32 * 68];   // [k][row] transposed, padded stride 68
    __shared__ float Ws[32 * 68];   // [k][col]

    const int tid = threadIdx.x;
    const int row0 = blockIdx.x * 64;
    const int ct = blockIdx.y;
    const int sx = tid & 15;        // col group
    const int sy = tid >> 4;        // row group

    float acc[16];
#pragma unroll
    for (int i = 0; i < 16; ++i) acc[i] = 0.0f;

    for (int kc = 0; kc < 8; ++kc) {
        __syncthreads();
        // Load X tile [64 rows][32 k] transposed into Xt[k][row]
#pragma unroll
        for (int it = 0; it < 2; ++it) {
            int fi = tid + it * 256;
            int r = fi >> 3, quad = fi & 7;
            float4 v = *(const float4*)(x + (size_t)(row0 + r) * CDIM + kc * 32 + quad * 4);
            Xt[(quad * 4 + 0) * 68 + r] = v.x;
            Xt[(quad * 4 + 1) * 68 + r] = v.y;
            Xt[(quad * 4 + 2) * 68 + r] = v.z;
            Xt[(quad * 4 + 3) * 68 + r] = v.w;
        }
        // Load W tile [32 k][64 cols]
#pragma unroll
        for (int it = 0; it < 2; ++it) {
            int fi = tid + it * 256;
            int k = fi >> 4, g = fi & 15;
            int krow = kc * 32 + k;
            float4 w;
            if (ct == 0) {
                if (g < 8) w = *(const float4*)(Wq + krow * FQ + g * 4);
                else       w = *(const float4*)(Wk + krow * FQ + (g - 8) * 4);
            } else {
                w = *(const float4*)(Wv + (size_t)krow * CDIM + (ct - 1) * 64 + g * 4);
            }
            *(float4*)(Ws + k * 68 + g * 4) = w;
        }
        __syncthreads();
#pragma unroll
        for (int kk = 0; kk < 32; ++kk) {
            float4 a = *(const float4*)(Xt + kk * 68 + sy * 4);
            float4 b = *(const float4*)(Ws + kk * 68 + sx * 4);
            acc[0]  += a.x * b.x; acc[1]  += a.x * b.y; acc[2]  += a.x * b.z; acc[3]  += a.x * b.w;
            acc[4]  += a.y * b.x; acc[5]  += a.y * b.y; acc[6]  += a.y * b.z; acc[7]  += a.y * b.w;
            acc[8]  += a.z * b.x; acc[9]  += a.z * b.y; acc[10] += a.z * b.z; acc[11] += a.z * b.w;
            acc[12] += a.w * b.x; acc[13] += a.w * b.y; acc[14] += a.w * b.z; acc[15] += a.w * b.w;
        }
    }

    // Epilogue: bias + ReLU, scatter to q/k/v scratch.
#pragma unroll
    for (int i = 0; i < 4; ++i) {
        int row = row0 + sy * 4 + i;
#pragma unroll
        for (int j = 0; j < 4; ++j) {
            int c = sx * 4 + j;
            float val = acc[i * 4 + j];
            if (ct == 0) {
                if (c < 32) g_q[(size_t)row * FQ + c]        = relu(val + bq[c]);
                else        g_k[(size_t)row * FQ + (c - 32)] = relu(val + bk[c - 32]);
            } else {
                int cc = (ct - 1) * 64 + c;
                g_v[(size_t)row * CDIM + cc] = relu(val + bv[cc]);
            }
        }
    }
}

// ---------------------------------------------------------------------------
// Kernel 2: fused flash attention (fp32, online softmax, unscaled logits).
// grid: (64 query tiles, 4 batches), 256 threads.
// Per key tile of 64: S = Q Kt (16 acc/thread, 16x16 thread grid),
// warp-shfl row max/sum, P -> smem transposed, PV with 8x8 register tile.
// ---------------------------------------------------------------------------
#define SM_QT   0
#define SM_KT   (32 * 68)
#define SM_VS   (2 * 32 * 68)
#define SM_PT   (2 * 32 * 68 + 64 * 256)
#define SM_M    (SM_PT + 64 * 68)
#define SM_L    (SM_M + 64)
#define SM_A    (SM_L + 64)
#define ATTN_SMEM_FLOATS (SM_A + 64)
#define ATTN_SMEM_BYTES  (ATTN_SMEM_FLOATS * 4)

__global__ __launch_bounds__(256, 2) void attn_kernel()
{
    extern __shared__ float sm[];
    float* Qt = sm + SM_QT;    // [32 d][64 r], stride 68
    float* Kt = sm + SM_KT;    // [32 d][64 j], stride 68
    float* Vs = sm + SM_VS;    // [64 j][256 c], stride 256
    float* Pt = sm + SM_PT;    // [64 j][64 r], stride 68
    float* mS = sm + SM_M;
    float* lS = sm + SM_L;
    float* aS = sm + SM_A;

    const int tid = threadIdx.x;
    const int b = blockIdx.y;
    const int q0 = blockIdx.x * 64;
    const int sx = tid & 15, sy = tid >> 4;   // S-phase coords
    const int tc = tid & 31, tr = tid >> 5;   // PV-phase coords

    const float* qb = g_q + (size_t)b * NTOK * FQ;
    const float* kb = g_k + (size_t)b * NTOK * FQ;
    const float* vb = g_v + (size_t)b * NTOK * CDIM;

    // Load Q tile transposed: Qt[d][r]
#pragma unroll
    for (int it = 0; it < 2; ++it) {
        int fi = tid + it * 256;
        int r = fi >> 3, quad = fi & 7;
        float4 v = *(const float4*)(qb + (size_t)(q0 + r) * FQ + quad * 4);
        Qt[(quad * 4 + 0) * 68 + r] = v.x;
        Qt[(quad * 4 + 1) * 68 + r] = v.y;
        Qt[(quad * 4 + 2) * 68 + r] = v.z;
        Qt[(quad * 4 + 3) * 68 + r] = v.w;
    }
    if (tid < 64) { mS[tid] = -1e30f; lS[tid] = 0.0f; }

    float O[64];
#pragma unroll
    for (int i = 0; i < 64; ++i) O[i] = 0.0f;

    for (int kt = 0; kt < 64; ++kt) {
        const int k0 = kt * 64;
        __syncthreads();   // previous PV done before overwriting Kt/Vs

        // Load K tile transposed: Kt[d][j]
#pragma unroll
        for (int it = 0; it < 2; ++it) {
            int fi = tid + it * 256;
            int j = fi >> 3, quad = fi & 7;
            float4 v = *(const float4*)(kb + (size_t)(k0 + j) * FQ + quad * 4);
            Kt[(quad * 4 + 0) * 68 + j] = v.x;
            Kt[(quad * 4 + 1) * 68 + j] = v.y;
            Kt[(quad * 4 + 2) * 68 + j] = v.z;
            Kt[(quad * 4 + 3) * 68 + j] = v.w;
        }
        // Load V tile (contiguous 64KB copy)
        {
            const float4* src = (const float4*)(vb + (size_t)k0 * CDIM);
            float4* dst = (float4*)Vs;
#pragma unroll
            for (int it = 0; it < 16; ++it) dst[tid + it * 256] = src[tid + it * 256];
        }
        __syncthreads();

        // ---- S = Q K^T (unscaled). Each thread: rows sy*4.., cols sx*4.. ----
        float s[16];
#pragma unroll
        for (int i = 0; i < 16; ++i) s[i] = 0.0f;
#pragma unroll
        for (int d = 0; d < 32; ++d) {
            float4 a = *(const float4*)(Qt + d * 68 + sy * 4);
            float4 k4 = *(const float4*)(Kt + d * 68 + sx * 4);
            s[0]  += a.x * k4.x; s[1]  += a.x * k4.y; s[2]  += a.x * k4.z; s[3]  += a.x * k4.w;
            s[4]  += a.y * k4.x; s[5]  += a.y * k4.y; s[6]  += a.y * k4.z; s[7]  += a.y * k4.w;
            s[8]  += a.z * k4.x; s[9]  += a.z * k4.y; s[10] += a.z * k4.z; s[11] += a.z * k4.w;
            s[12] += a.w * k4.x; s[13] += a.w * k4.y; s[14] += a.w * k4.z; s[15] += a.w * k4.w;
        }

        // ---- online softmax over this key tile (rows owned by 16-lane groups) ----
#pragma unroll
        for (int i = 0; i < 4; ++i) {
            float rm = fmaxf(fmaxf(s[i * 4], s[i * 4 + 1]), fmaxf(s[i * 4 + 2], s[i * 4 + 3]));
            rm = fmaxf(rm, __shfl_xor_sync(0xffffffffu, rm, 1));
            rm = fmaxf(rm, __shfl_xor_sync(0xffffffffu, rm, 2));
            rm = fmaxf(rm, __shfl_xor_sync(0xffffffffu, rm, 4));
            rm = fmaxf(rm, __shfl_xor_sync(0xffffffffu, rm, 8));
            int r = sy * 4 + i;
            float mprev = mS[r];
            float mnew = fmaxf(mprev, rm);
            float p0 = __expf(s[i * 4 + 0] - mnew);
            float p1 = __expf(s[i * 4 + 1] - mnew);
            float p2 = __expf(s[i * 4 + 2] - mnew);
            float p3 = __expf(s[i * 4 + 3] - mnew);
            float rs = (p0 + p1) + (p2 + p3);
            rs += __shfl_xor_sync(0xffffffffu, rs, 1);
            rs += __shfl_xor_sync(0xffffffffu, rs, 2);
            rs += __shfl_xor_sync(0xffffffffu, rs, 4);
            rs += __shfl_xor_sync(0xffffffffu, rs, 8);
            float alpha = __expf(mprev - mnew);
            if (sx == 0) {
                mS[r] = mnew;
                lS[r] = lS[r] * alpha + rs;
                aS[r] = alpha;
            }
            s[i * 4 + 0] = p0; s[i * 4 + 1] = p1; s[i * 4 + 2] = p2; s[i * 4 + 3] = p3;
        }
        // write P transposed: Pt[j][r]
#pragma unroll
        for (int jj = 0; jj < 4; ++jj) {
            float4 pv = make_float4(s[0 * 4 + jj], s[1 * 4 + jj], s[2 * 4 + jj], s[3 * 4 + jj]);
            *(float4*)(Pt + (sx * 4 + jj) * 68 + sy * 4) = pv;
        }
        __syncthreads();

        // ---- O = O*alpha + P V. rows tr*8.., cols {tc*4.., 128+tc*4..} ----
        float al[8];
#pragma unroll
        for (int i = 0; i < 8; ++i) al[i] = aS[tr * 8 + i];
#pragma unroll
        for (int i = 0; i < 8; ++i)
#pragma unroll
            for (int j = 0; j < 8; ++j) O[i * 8 + j] *= al[i];

#pragma unroll 4
        for (int jj = 0; jj < 64; ++jj) {
            float4 pA = *(const float4*)(Pt + jj * 68 + tr * 8);
            float4 pB = *(const float4*)(Pt + jj * 68 + tr * 8 + 4);
            float4 v0 = *(const float4*)(Vs + jj * 256 + tc * 4);
            float4 v1 = *(const float4*)(Vs + jj * 256 + 128 + tc * 4);
            float p[8] = {pA.x, pA.y, pA.z, pA.w, pB.x, pB.y, pB.z, pB.w};
#pragma unroll
            for (int i = 0; i < 8; ++i) {
                O[i * 8 + 0] += p[i] * v0.x;
                O[i * 8 + 1] += p[i] * v0.y;
                O[i * 8 + 2] += p[i] * v0.z;
                O[i * 8 + 3] += p[i] * v0.w;
                O[i * 8 + 4] += p[i] * v1.x;
                O[i * 8 + 5] += p[i] * v1.y;
                O[i * 8 + 6] += p[i] * v1.z;
                O[i * 8 + 7] += p[i] * v1.w;
            }
        }
    }

    // ---- normalize and write attended ----
#pragma unroll
    for (int i = 0; i < 8; ++i) {
        int r = tr * 8 + i;
        float inv = 1.0f / lS[r];
        float* dst = g_att + ((size_t)b * NTOK + q0 + r) * CDIM;
        float4 o0 = make_float4(O[i * 8 + 0] * inv, O[i * 8 + 1] * inv,
                                O[i * 8 + 2] * inv, O[i * 8 + 3] * inv);
        float4 o1 = make_float4(O[i * 8 + 4] * inv, O[i * 8 + 5] * inv,
                                O[i * 8 + 6] * inv, O[i * 8 + 7] * inv);
        *(float4*)(dst + tc * 4) = o0;
        *(float4*)(dst + 128 + tc * 4) = o1;
    }
}

// ---------------------------------------------------------------------------
// Kernel 3: output projection + ReLU + residual.
// out = inputs + relu(attended @ Wo + bo).  grid: (256 row tiles, 4 col tiles)
// ---------------------------------------------------------------------------
__global__ __launch_bounds__(256) void out_kernel(
    const float* __restrict__ x,
    const float* __restrict__ Wo, const float* __restrict__ bo,
    float* __restrict__ out)
{
    __shared__ float At[32 * 68];
    __shared__ float Ws[32 * 68];

    const int tid = threadIdx.x;
    const int row0 = blockIdx.x * 64;
    const int c0 = blockIdx.y * 64;
    const int sx = tid & 15, sy = tid >> 4;

    float acc[16];
#pragma unroll
    for (int i = 0; i < 16; ++i) acc[i] = 0.0f;

    for (int kc = 0; kc < 8; ++kc) {
        __syncthreads();
#pragma unroll
        for (int it = 0; it < 2; ++it) {
            int fi = tid + it * 256;
            int r = fi >> 3, quad = fi & 7;
            float4 v = *(const float4*)(g_att + (size_t)(row0 + r) * CDIM + kc * 32 + quad * 4);
            At[(quad * 4 + 0) * 68 + r] = v.x;
            At[(quad * 4 + 1) * 68 + r] = v.y;
            At[(quad * 4 + 2) * 68 + r] = v.z;
            At[(quad * 4 + 3) * 68 + r] = v.w;
        }
#pragma unroll
        for (int it = 0; it < 2; ++it) {
            int fi = tid + it * 256;
            int k = fi >> 4, g = fi & 15;
            float4 w = *(const float4*)(Wo + (size_t)(kc * 32 + k) * CDIM + c0 + g * 4);
            *(float4*)(Ws + k * 68 + g * 4) = w;
        }
        __syncthreads();
#pragma unroll
        for (int kk = 0; kk < 32; ++kk) {
            float4 a = *(const float4*)(At + kk * 68 + sy * 4);
            float4 b = *(const float4*)(Ws + kk * 68 + sx * 4);
            acc[0]  += a.x * b.x; acc[1]  += a.x * b.y; acc[2]  += a.x * b.z; acc[3]  += a.x * b.w;
            acc[4]  += a.y * b.x; acc[5]  += a.y * b.y; acc[6]  += a.y * b.z; acc[7]  += a.y * b.w;
            acc[8]  += a.z * b.x; acc[9]  += a.z * b.y; acc[10] += a.z * b.z; acc[11] += a.z * b.w;
            acc[12] += a.w * b.x; acc[13] += a.w * b.y; acc[14] += a.w * b.z; acc[15] += a.w * b.w;
        }
    }

#pragma unroll
    for (int i = 0; i < 4; ++i) {
        int row = row0 + sy * 4 + i;
#pragma unroll
        for (int j = 0; j < 4; ++j) {
            int cc = c0 + sx * 4 + j;
            float val = relu(acc[i * 4 + j] + bo[cc]);
            out[(size_t)row * CDIM + cc] = x[(size_t)row * CDIM + cc] + val;
        }
    }
}

// ---------------------------------------------------------------------------
extern "C" void kernel_launch(void* const* d_in, const int* in_sizes, int n_in,
                              void* d_out, int out_size)
{
    const float* x  = (const float*)d_in[0];
    const float* Wq = (const float*)d_in[1];
    const float* bq = (const float*)d_in[2];
    const float* Wk = (const float*)d_in[3];
    const float* bk = (const float*)d_in[4];
    const float* Wv = (const float*)d_in[5];
    const float* bv = (const float*)d_in[6];
    const float* Wo = (const float*)d_in[7];
    const float* bo = (const float*)d_in[8];
    float* out = (float*)d_out;

    cudaFuncSetAttribute(attn_kernel, cudaFuncAttributeMaxDynamicSharedMemorySize,
                         ATTN_SMEM_BYTES);

    qkv_kernel<<<dim3(256, 5), 256>>>(x, Wq, bq, Wk, bk, Wv, bv);
    attn_kernel<<<dim3(64, 4), 256, ATTN_SMEM_BYTES>>>();
    out_kernel<<<dim3(256, 4), 256>>>(x, Wo, bo, out);
}

// round 10
// speedup vs baseline: 1.9345x; 1.9345x over previous
#include <cuda_runtime.h>
#include <cstdint>

// Shapes: B=4, H=W=64 -> N=4096 tokens per batch, C=256, FQ=32.
#define BATCH 4
#define NTOK 4096
#define CDIM 256
#define FQ 32
#define ROWS_TOTAL (BATCH * NTOK)   // 16384

// Scratch (no allocations allowed -> __device__ globals)
__device__ float g_q[ROWS_TOTAL * FQ];
__device__ float g_k[ROWS_TOTAL * FQ];
__device__ float g_v[ROWS_TOTAL * CDIM];
__device__ float g_att[ROWS_TOTAL * CDIM];

__device__ __forceinline__ float relu(float v) { return v > 0.0f ? v : 0.0f; }

__device__ __forceinline__ uint32_t f2tf32(float f) {
    uint32_t r;
    asm("cvt.rna.tf32.f32 %0, %1;" : "=r"(r) : "f"(f));
    return r;
}

// ---------------------------------------------------------------------------
// Kernel 1: fused QKV projection (fp32, unchanged — 88us).
// ---------------------------------------------------------------------------
__global__ __launch_bounds__(256) void qkv_kernel(
    const float* __restrict__ x,
    const float* __restrict__ Wq, const float* __restrict__ bq,
    const float* __restrict__ Wk, const float* __restrict__ bk,
    const float* __restrict__ Wv, const float* __restrict__ bv)
{
    __shared__ float Xt[32 * 68];
    __shared__ float Ws[32 * 68];

    const int tid = threadIdx.x;
    const int row0 = blockIdx.x * 64;
    const int ct = blockIdx.y;
    const int sx = tid & 15;
    const int sy = tid >> 4;

    float acc[16];
#pragma unroll
    for (int i = 0; i < 16; ++i) acc[i] = 0.0f;

    for (int kc = 0; kc < 8; ++kc) {
        __syncthreads();
#pragma unroll
        for (int it = 0; it < 2; ++it) {
            int fi = tid + it * 256;
            int r = fi >> 3, quad = fi & 7;
            float4 v = *(const float4*)(x + (size_t)(row0 + r) * CDIM + kc * 32 + quad * 4);
            Xt[(quad * 4 + 0) * 68 + r] = v.x;
            Xt[(quad * 4 + 1) * 68 + r] = v.y;
            Xt[(quad * 4 + 2) * 68 + r] = v.z;
            Xt[(quad * 4 + 3) * 68 + r] = v.w;
        }
#pragma unroll
        for (int it = 0; it < 2; ++it) {
            int fi = tid + it * 256;
            int k = fi >> 4, g = fi & 15;
            int krow = kc * 32 + k;
            float4 w;
            if (ct == 0) {
                if (g < 8) w = *(const float4*)(Wq + krow * FQ + g * 4);
                else       w = *(const float4*)(Wk + krow * FQ + (g - 8) * 4);
            } else {
                w = *(const float4*)(Wv + (size_t)krow * CDIM + (ct - 1) * 64 + g * 4);
            }
            *(float4*)(Ws + k * 68 + g * 4) = w;
        }
        __syncthreads();
#pragma unroll
        for (int kk = 0; kk < 32; ++kk) {
            float4 a = *(const float4*)(Xt + kk * 68 + sy * 4);
            float4 b = *(const float4*)(Ws + kk * 68 + sx * 4);
            acc[0]  += a.x * b.x; acc[1]  += a.x * b.y; acc[2]  += a.x * b.z; acc[3]  += a.x * b.w;
            acc[4]  += a.y * b.x; acc[5]  += a.y * b.y; acc[6]  += a.y * b.z; acc[7]  += a.y * b.w;
            acc[8]  += a.z * b.x; acc[9]  += a.z * b.y; acc[10] += a.z * b.z; acc[11] += a.z * b.w;
            acc[12] += a.w * b.x; acc[13] += a.w * b.y; acc[14] += a.w * b.z; acc[15] += a.w * b.w;
        }
    }

#pragma unroll
    for (int i = 0; i < 4; ++i) {
        int row = row0 + sy * 4 + i;
#pragma unroll
        for (int j = 0; j < 4; ++j) {
            int c = sx * 4 + j;
            float val = acc[i * 4 + j];
            if (ct == 0) {
                if (c < 32) g_q[(size_t)row * FQ + c]        = relu(val + bq[c]);
                else        g_k[(size_t)row * FQ + (c - 32)] = relu(val + bk[c - 32]);
            } else {
                int cc = (ct - 1) * 64 + c;
                g_v[(size_t)row * CDIM + cc] = relu(val + bv[cc]);
            }
        }
    }
}

// ---------------------------------------------------------------------------
// Kernel 2: flash attention. S = QK^T in fp32 (exact logits), online softmax
// in fp32, PV via mma.sync tf32 tensor cores with fp32 accumulation.
//
// Smem: Qt/Kt [32][68] transposed; Vs [64 j][264] tf32 (stride 264 -> B-frag
// LDS banks 8*tig+gID, conflict-free); Ps [64 r][68] tf32 row-major (A-frag
// banks 4*gID+tig, conflict-free).
//
// PV warp tile: 32 rows x 64 cols = 2 m-tiles x 8 n-tiles of m16n8k8.
// ---------------------------------------------------------------------------
#define SM_QT   0
#define SM_KT   (32 * 68)
#define SM_VS   (2 * 32 * 68)
#define SM_PS   (SM_VS + 64 * 264)
#define SM_M    (SM_PS + 64 * 68)
#define SM_L    (SM_M + 64)
#define SM_A    (SM_L + 64)
#define ATTN_SMEM_FLOATS (SM_A + 64)
#define ATTN_SMEM_BYTES  (ATTN_SMEM_FLOATS * 4)

__global__ __launch_bounds__(256, 2) void attn_kernel()
{
    extern __shared__ float sm[];
    float* Qt = sm + SM_QT;
    float* Kt = sm + SM_KT;
    float* Vs = sm + SM_VS;   // tf32 bits
    float* Ps = sm + SM_PS;   // tf32 bits
    float* mS = sm + SM_M;
    float* lS = sm + SM_L;
    float* aS = sm + SM_A;

    const int tid = threadIdx.x;
    const int b = blockIdx.y;
    const int q0 = blockIdx.x * 64;
    const int sx = tid & 15, sy = tid >> 4;       // S-phase coords
    const int lane = tid & 31, warp = tid >> 5;   // PV-phase coords
    const int wr = (warp & 1) * 32;               // warp row base
    const int wc = (warp >> 1) * 64;              // warp col base
    const int gID = lane >> 2, tig = lane & 3;

    const float* qb = g_q + (size_t)b * NTOK * FQ;
    const float* kb = g_k + (size_t)b * NTOK * FQ;
    const float* vb = g_v + (size_t)b * NTOK * CDIM;

    // Load Q tile transposed: Qt[d][r]
#pragma unroll
    for (int it = 0; it < 2; ++it) {
        int fi = tid + it * 256;
        int r = fi >> 3, quad = fi & 7;
        float4 v = *(const float4*)(qb + (size_t)(q0 + r) * FQ + quad * 4);
        Qt[(quad * 4 + 0) * 68 + r] = v.x;
        Qt[(quad * 4 + 1) * 68 + r] = v.y;
        Qt[(quad * 4 + 2) * 68 + r] = v.z;
        Qt[(quad * 4 + 3) * 68 + r] = v.w;
    }
    if (tid < 64) { mS[tid] = -1e30f; lS[tid] = 0.0f; }

    // O accumulators: [mt(2)][nt(8)][4]  (mma C fragments)
    float O[64];
#pragma unroll
    for (int i = 0; i < 64; ++i) O[i] = 0.0f;

    for (int kt = 0; kt < 64; ++kt) {
        const int k0 = kt * 64;
        __syncthreads();   // previous PV done before overwriting Kt/Vs

        // Load K tile transposed: Kt[d][j]
#pragma unroll
        for (int it = 0; it < 2; ++it) {
            int fi = tid + it * 256;
            int j = fi >> 3, quad = fi & 7;
            float4 v = *(const float4*)(kb + (size_t)(k0 + j) * FQ + quad * 4);
            Kt[(quad * 4 + 0) * 68 + j] = v.x;
            Kt[(quad * 4 + 1) * 68 + j] = v.y;
            Kt[(quad * 4 + 2) * 68 + j] = v.z;
            Kt[(quad * 4 + 3) * 68 + j] = v.w;
        }
        // Load V tile, convert to tf32, store with stride 264
        {
            const float4* src = (const float4*)(vb + (size_t)k0 * CDIM);
#pragma unroll
            for (int it = 0; it < 16; ++it) {
                int fi = tid + it * 256;
                int j = fi >> 6, c4 = fi & 63;
                float4 v = src[fi];
                uint4 t;
                t.x = f2tf32(v.x); t.y = f2tf32(v.y);
                t.z = f2tf32(v.z); t.w = f2tf32(v.w);
                *(uint4*)(Vs + j * 264 + c4 * 4) = t;
            }
        }
        __syncthreads();

        // ---- S = Q K^T (fp32). Thread: rows sy*4.., cols sx*4.. ----
        float s[16];
#pragma unroll
        for (int i = 0; i < 16; ++i) s[i] = 0.0f;
#pragma unroll
        for (int d = 0; d < 32; ++d) {
            float4 a = *(const float4*)(Qt + d * 68 + sy * 4);
            float4 k4 = *(const float4*)(Kt + d * 68 + sx * 4);
            s[0]  += a.x * k4.x; s[1]  += a.x * k4.y; s[2]  += a.x * k4.z; s[3]  += a.x * k4.w;
            s[4]  += a.y * k4.x; s[5]  += a.y * k4.y; s[6]  += a.y * k4.z; s[7]  += a.y * k4.w;
            s[8]  += a.z * k4.x; s[9]  += a.z * k4.y; s[10] += a.z * k4.z; s[11] += a.z * k4.w;
            s[12] += a.w * k4.x; s[13] += a.w * k4.y; s[14] += a.w * k4.z; s[15] += a.w * k4.w;
        }

        // ---- online softmax over this key tile ----
#pragma unroll
        for (int i = 0; i < 4; ++i) {
            float rm = fmaxf(fmaxf(s[i * 4], s[i * 4 + 1]), fmaxf(s[i * 4 + 2], s[i * 4 + 3]));
            rm = fmaxf(rm, __shfl_xor_sync(0xffffffffu, rm, 1));
            rm = fmaxf(rm, __shfl_xor_sync(0xffffffffu, rm, 2));
            rm = fmaxf(rm, __shfl_xor_sync(0xffffffffu, rm, 4));
            rm = fmaxf(rm, __shfl_xor_sync(0xffffffffu, rm, 8));
            int r = sy * 4 + i;
            float mprev = mS[r];
            float mnew = fmaxf(mprev, rm);
            float p0 = __expf(s[i * 4 + 0] - mnew);
            float p1 = __expf(s[i * 4 + 1] - mnew);
            float p2 = __expf(s[i * 4 + 2] - mnew);
            float p3 = __expf(s[i * 4 + 3] - mnew);
            float rs = (p0 + p1) + (p2 + p3);
            rs += __shfl_xor_sync(0xffffffffu, rs, 1);
            rs += __shfl_xor_sync(0xffffffffu, rs, 2);
            rs += __shfl_xor_sync(0xffffffffu, rs, 4);
            rs += __shfl_xor_sync(0xffffffffu, rs, 8);
            float alpha = __expf(mprev - mnew);
            if (sx == 0) {
                mS[r] = mnew;
                lS[r] = lS[r] * alpha + rs;
                aS[r] = alpha;
            }
            s[i * 4 + 0] = p0; s[i * 4 + 1] = p1; s[i * 4 + 2] = p2; s[i * 4 + 3] = p3;
        }
        // write P row-major as tf32: Ps[r][j]
#pragma unroll
        for (int i = 0; i < 4; ++i) {
            uint4 pv;
            pv.x = f2tf32(s[i * 4 + 0]);
            pv.y = f2tf32(s[i * 4 + 1]);
            pv.z = f2tf32(s[i * 4 + 2]);
            pv.w = f2tf32(s[i * 4 + 3]);
            *(uint4*)(Ps + (sy * 4 + i) * 68 + sx * 4) = pv;
        }
        __syncthreads();

        // ---- O = O*alpha + P V  (tensor cores, tf32 x tf32 -> fp32) ----
        float al[4];
        al[0] = aS[wr + gID];
        al[1] = aS[wr + gID + 8];
        al[2] = aS[wr + 16 + gID];
        al[3] = aS[wr + 24 + gID];
#pragma unroll
        for (int mt = 0; mt < 2; ++mt)
#pragma unroll
            for (int nt = 0; nt < 8; ++nt) {
                float* o = O + (mt * 8 + nt) * 4;
                o[0] *= al[mt * 2]; o[1] *= al[mt * 2];
                o[2] *= al[mt * 2 + 1]; o[3] *= al[mt * 2 + 1];
            }

        const uint32_t* Pu = (const uint32_t*)Ps;
        const uint32_t* Vu = (const uint32_t*)Vs;
#pragma unroll
        for (int kk = 0; kk < 8; ++kk) {
            const int j0 = kk * 8;
            uint32_t A[2][4];
#pragma unroll
            for (int mt = 0; mt < 2; ++mt) {
                int r0 = wr + mt * 16 + gID;
                A[mt][0] = Pu[r0 * 68 + j0 + tig];
                A[mt][1] = Pu[(r0 + 8) * 68 + j0 + tig];
                A[mt][2] = Pu[r0 * 68 + j0 + tig + 4];
                A[mt][3] = Pu[(r0 + 8) * 68 + j0 + tig + 4];
            }
#pragma unroll
            for (int nt = 0; nt < 8; ++nt) {
                int n = wc + nt * 8 + gID;
                uint32_t B0 = Vu[(j0 + tig) * 264 + n];
                uint32_t B1 = Vu[(j0 + tig + 4) * 264 + n];
#pragma unroll
                for (int mt = 0; mt < 2; ++mt) {
                    float* o = O + (mt * 8 + nt) * 4;
                    asm volatile(
                        "mma.sync.aligned.m16n8k8.row.col.f32.tf32.tf32.f32 "
                        "{%0,%1,%2,%3}, {%4,%5,%6,%7}, {%8,%9}, {%0,%1,%2,%3};"
                        : "+f"(o[0]), "+f"(o[1]), "+f"(o[2]), "+f"(o[3])
                        : "r"(A[mt][0]), "r"(A[mt][1]), "r"(A[mt][2]), "r"(A[mt][3]),
                          "r"(B0), "r"(B1));
                }
            }
        }
    }

    // ---- normalize and write attended ----
#pragma unroll
    for (int mt = 0; mt < 2; ++mt) {
        int r0 = wr + mt * 16 + gID;
        int r1 = r0 + 8;
        float inv0 = 1.0f / lS[r0];
        float inv1 = 1.0f / lS[r1];
        float* d0 = g_att + ((size_t)b * NTOK + q0 + r0) * CDIM;
        float* d1 = g_att + ((size_t)b * NTOK + q0 + r1) * CDIM;
#pragma unroll
        for (int nt = 0; nt < 8; ++nt) {
            float* o = O + (mt * 8 + nt) * 4;
            int c = wc + nt * 8 + tig * 2;
            *(float2*)(d0 + c) = make_float2(o[0] * inv0, o[1] * inv0);
            *(float2*)(d1 + c) = make_float2(o[2] * inv1, o[3] * inv1);
        }
    }
}

// ---------------------------------------------------------------------------
// Kernel 3: output projection + ReLU + residual (fp32, unchanged).
// ---------------------------------------------------------------------------
__global__ __launch_bounds__(256) void out_kernel(
    const float* __restrict__ x,
    const float* __restrict__ Wo, const float* __restrict__ bo,
    float* __restrict__ out)
{
    __shared__ float At[32 * 68];
    __shared__ float Ws[32 * 68];

    const int tid = threadIdx.x;
    const int row0 = blockIdx.x * 64;
    const int c0 = blockIdx.y * 64;
    const int sx = tid & 15, sy = tid >> 4;

    float acc[16];
#pragma unroll
    for (int i = 0; i < 16; ++i) acc[i] = 0.0f;

    for (int kc = 0; kc < 8; ++kc) {
        __syncthreads();
#pragma unroll
        for (int it = 0; it < 2; ++it) {
            int fi = tid + it * 256;
            int r = fi >> 3, quad = fi & 7;
            float4 v = *(const float4*)(g_att + (size_t)(row0 + r) * CDIM + kc * 32 + quad * 4);
            At[(quad * 4 + 0) * 68 + r] = v.x;
            At[(quad * 4 + 1) * 68 + r] = v.y;
            At[(quad * 4 + 2) * 68 + r] = v.z;
            At[(quad * 4 + 3) * 68 + r] = v.w;
        }
#pragma unroll
        for (int it = 0; it < 2; ++it) {
            int fi = tid + it * 256;
            int k = fi >> 4, g = fi & 15;
            float4 w = *(const float4*)(Wo + (size_t)(kc * 32 + k) * CDIM + c0 + g * 4);
            *(float4*)(Ws + k * 68 + g * 4) = w;
        }
        __syncthreads();
#pragma unroll
        for (int kk = 0; kk < 32; ++kk) {
            float4 a = *(const float4*)(At + kk * 68 + sy * 4);
            float4 b = *(const float4*)(Ws + kk * 68 + sx * 4);
            acc[0]  += a.x * b.x; acc[1]  += a.x * b.y; acc[2]  += a.x * b.z; acc[3]  += a.x * b.w;
            acc[4]  += a.y * b.x; acc[5]  += a.y * b.y; acc[6]  += a.y * b.z; acc[7]  += a.y * b.w;
            acc[8]  += a.z * b.x; acc[9]  += a.z * b.y; acc[10] += a.z * b.z; acc[11] += a.z * b.w;
            acc[12] += a.w * b.x; acc[13] += a.w * b.y; acc[14] += a.w * b.z; acc[15] += a.w * b.w;
        }
    }

#pragma unroll
    for (int i = 0; i < 4; ++i) {
        int row = row0 + sy * 4 + i;
#pragma unroll
        for (int j = 0; j < 4; ++j) {
            int cc = c0 + sx * 4 + j;
            float val = relu(acc[i * 4 + j] + bo[cc]);
            out[(size_t)row * CDIM + cc] = x[(size_t)row * CDIM + cc] + val;
        }
    }
}

// ---------------------------------------------------------------------------
extern "C" void kernel_launch(void* const* d_in, const int* in_sizes, int n_in,
                              void* d_out, int out_size)
{
    const float* x  = (const float*)d_in[0];
    const float* Wq = (const float*)d_in[1];
    const float* bq = (const float*)d_in[2];
    const float* Wk = (const float*)d_in[3];
    const float* bk = (const float*)d_in[4];
    const float* Wv = (const float*)d_in[5];
    const float* bv = (const float*)d_in[6];
    const float* Wo = (const float*)d_in[7];
    const float* bo = (const float*)d_in[8];
    float* out = (float*)d_out;

    cudaFuncSetAttribute(attn_kernel, cudaFuncAttributeMaxDynamicSharedMemorySize,
                         ATTN_SMEM_BYTES);

    qkv_kernel<<<dim3(256, 5), 256>>>(x, Wq, bq, Wk, bk, Wv, bv);
    attn_kernel<<<dim3(64, 4), 256, ATTN_SMEM_BYTES>>>();
    out_kernel<<<dim3(256, 4), 256>>>(x, Wo, bo, out);
}

// round 12
// speedup vs baseline: 2.4185x; 1.2502x over previous
#include <cuda_runtime.h>
#include <cstdint>

// Shapes: B=4, H=W=64 -> N=4096 tokens per batch, C=256, FQ=32.
#define BATCH 4
#define NTOK 4096
#define CDIM 256
#define FQ 32
#define ROWS_TOTAL (BATCH * NTOK)   // 16384

// Scratch (no allocations allowed -> __device__ globals)
__device__ float g_q[ROWS_TOTAL * FQ];
__device__ float g_k[ROWS_TOTAL * FQ];
__device__ float g_v[ROWS_TOTAL * CDIM];
__device__ float g_att[ROWS_TOTAL * CDIM];

__device__ __forceinline__ float relu(float v) { return v > 0.0f ? v : 0.0f; }

__device__ __forceinline__ uint32_t f2tf32(float f) {
    uint32_t r;
    asm("cvt.rna.tf32.f32 %0, %1;" : "=r"(r) : "f"(f));
    return r;
}

// ---------------------------------------------------------------------------
// Kernel 1: fused QKV projection (fp32, unchanged).
// ---------------------------------------------------------------------------
__global__ __launch_bounds__(256) void qkv_kernel(
    const float* __restrict__ x,
    const float* __restrict__ Wq, const float* __restrict__ bq,
    const float* __restrict__ Wk, const float* __restrict__ bk,
    const float* __restrict__ Wv, const float* __restrict__ bv)
{
    __shared__ float Xt[32 * 68];
    __shared__ float Ws[32 * 68];

    const int tid = threadIdx.x;
    const int row0 = blockIdx.x * 64;
    const int ct = blockIdx.y;
    const int sx = tid & 15;
    const int sy = tid >> 4;

    float acc[16];
#pragma unroll
    for (int i = 0; i < 16; ++i) acc[i] = 0.0f;

    for (int kc = 0; kc < 8; ++kc) {
        __syncthreads();
#pragma unroll
        for (int it = 0; it < 2; ++it) {
            int fi = tid + it * 256;
            int r = fi >> 3, quad = fi & 7;
            float4 v = *(const float4*)(x + (size_t)(row0 + r) * CDIM + kc * 32 + quad * 4);
            Xt[(quad * 4 + 0) * 68 + r] = v.x;
            Xt[(quad * 4 + 1) * 68 + r] = v.y;
            Xt[(quad * 4 + 2) * 68 + r] = v.z;
            Xt[(quad * 4 + 3) * 68 + r] = v.w;
        }
#pragma unroll
        for (int it = 0; it < 2; ++it) {
            int fi = tid + it * 256;
            int k = fi >> 4, g = fi & 15;
            int krow = kc * 32 + k;
            float4 w;
            if (ct == 0) {
                if (g < 8) w = *(const float4*)(Wq + krow * FQ + g * 4);
                else       w = *(const float4*)(Wk + krow * FQ + (g - 8) * 4);
            } else {
                w = *(const float4*)(Wv + (size_t)krow * CDIM + (ct - 1) * 64 + g * 4);
            }
            *(float4*)(Ws + k * 68 + g * 4) = w;
        }
        __syncthreads();
#pragma unroll
        for (int kk = 0; kk < 32; ++kk) {
            float4 a = *(const float4*)(Xt + kk * 68 + sy * 4);
            float4 b = *(const float4*)(Ws + kk * 68 + sx * 4);
            acc[0]  += a.x * b.x; acc[1]  += a.x * b.y; acc[2]  += a.x * b.z; acc[3]  += a.x * b.w;
            acc[4]  += a.y * b.x; acc[5]  += a.y * b.y; acc[6]  += a.y * b.z; acc[7]  += a.y * b.w;
            acc[8]  += a.z * b.x; acc[9]  += a.z * b.y; acc[10] += a.z * b.z; acc[11] += a.z * b.w;
            acc[12] += a.w * b.x; acc[13] += a.w * b.y; acc[14] += a.w * b.z; acc[15] += a.w * b.w;
        }
    }

#pragma unroll
    for (int i = 0; i < 4; ++i) {
        int row = row0 + sy * 4 + i;
#pragma unroll
        for (int j = 0; j < 4; ++j) {
            int c = sx * 4 + j;
            float val = acc[i * 4 + j];
            if (ct == 0) {
                if (c < 32) g_q[(size_t)row * FQ + c]        = relu(val + bq[c]);
                else        g_k[(size_t)row * FQ + (c - 32)] = relu(val + bk[c - 32]);
            } else {
                int cc = (ct - 1) * 64 + c;
                g_v[(size_t)row * CDIM + cc] = relu(val + bv[cc]);
            }
        }
    }
}

// ---------------------------------------------------------------------------
// Kernel 2: flash attention, fully tensor-core.
// S = QK^T via mma tf32 (Qs/Ks stride 36: fragment banks 4*gID+tig, clean),
// softmax on fragments (shfl over tig lanes + smem cross-warp combine),
// PV via mma tf32 (Ps stride 68, Vs stride 264 — both conflict-free loads).
// ---------------------------------------------------------------------------
#define SM_QS   0
#define SM_KS   (SM_QS + 64 * 36)
#define SM_VS   (SM_KS + 64 * 36)
#define SM_PS   (SM_VS + 64 * 264)
#define SM_M    (SM_PS + 64 * 68)
#define SM_L    (SM_M + 64)
#define SM_A    (SM_L + 64)
#define SM_PMX  (SM_A + 64)
#define SM_PSM  (SM_PMX + 128)
#define ATTN_SMEM_FLOATS (SM_PSM + 128)
#define ATTN_SMEM_BYTES  (ATTN_SMEM_FLOATS * 4)

__global__ __launch_bounds__(256, 2) void attn_kernel()
{
    extern __shared__ float sm[];
    float* Qs = sm + SM_QS;     // tf32 bits, [64 r][36]
    float* Ks = sm + SM_KS;     // tf32 bits, [64 j][36]
    float* Vs = sm + SM_VS;     // tf32 bits, [64 j][264]
    float* Ps = sm + SM_PS;     // tf32 bits, [64 r][68]
    float* mS = sm + SM_M;
    float* lS = sm + SM_L;
    float* aS = sm + SM_A;
    float* pmx = sm + SM_PMX;   // [2][64]
    float* psm = sm + SM_PSM;   // [2][64]

    const int tid = threadIdx.x;
    const int b = blockIdx.y;
    const int q0 = blockIdx.x * 64;
    const int lane = tid & 31, warp = tid >> 5;
    const int gID = lane >> 2, tig = lane & 3;
    // S-phase: warp strip 16 rows x 32 cols
    const int srow0 = (warp & 3) * 16;
    const int scol0 = (warp >> 2) * 32;
    const int shalf = warp >> 2;              // 0/1: which 32-col half
    // PV-phase: warp tile 32 rows x 64 cols
    const int wr = (warp & 1) * 32;
    const int wc = (warp >> 1) * 64;

    const float* qb = g_q + (size_t)b * NTOK * FQ;
    const float* kb = g_k + (size_t)b * NTOK * FQ;
    const float* vb = g_v + (size_t)b * NTOK * CDIM;

    // Load Q tile -> Qs row-major tf32, stride 36
#pragma unroll
    for (int it = 0; it < 2; ++it) {
        int fi = tid + it * 256;
        int r = fi >> 3, quad = fi & 7;
        float4 v = *(const float4*)(qb + (size_t)(q0 + r) * FQ + quad * 4);
        uint4 t;
        t.x = f2tf32(v.x); t.y = f2tf32(v.y); t.z = f2tf32(v.z); t.w = f2tf32(v.w);
        *(uint4*)(Qs + r * 36 + quad * 4) = t;
    }
    if (tid < 64) { mS[tid] = -1e30f; lS[tid] = 0.0f; }

    // PV accumulators: [mt(2)][nt(8)][4]
    float O[64];
#pragma unroll
    for (int i = 0; i < 64; ++i) O[i] = 0.0f;

    const uint32_t* Qu = (const uint32_t*)Qs;
    const uint32_t* Ku = (const uint32_t*)Ks;
    const uint32_t* Pu = (const uint32_t*)Ps;
    const uint32_t* Vu = (const uint32_t*)Vs;

    for (int kt = 0; kt < 64; ++kt) {
        const int k0 = kt * 64;
        __syncthreads();   // prev PV done; Q ready (iter 0)

        // K tile -> Ks row-major tf32, stride 36
#pragma unroll
        for (int it = 0; it < 2; ++it) {
            int fi = tid + it * 256;
            int j = fi >> 3, quad = fi & 7;
            float4 v = *(const float4*)(kb + (size_t)(k0 + j) * FQ + quad * 4);
            uint4 t;
            t.x = f2tf32(v.x); t.y = f2tf32(v.y); t.z = f2tf32(v.z); t.w = f2tf32(v.w);
            *(uint4*)(Ks + j * 36 + quad * 4) = t;
        }
        // V tile -> Vs tf32, stride 264
        {
            const float4* src = (const float4*)(vb + (size_t)k0 * CDIM);
#pragma unroll
            for (int it = 0; it < 16; ++it) {
                int fi = tid + it * 256;
                int j = fi >> 6, c4 = fi & 63;
                float4 v = src[fi];
                uint4 t;
                t.x = f2tf32(v.x); t.y = f2tf32(v.y);
                t.z = f2tf32(v.z); t.w = f2tf32(v.w);
                *(uint4*)(Vs + j * 264 + c4 * 4) = t;
            }
        }
        __syncthreads();

        // ---- S = Q K^T via tensor cores. Warp strip 16x32. ----
        float c[16];
#pragma unroll
        for (int i = 0; i < 16; ++i) c[i] = 0.0f;
#pragma unroll
        for (int kks = 0; kks < 4; ++kks) {
            const int d0 = kks * 8;
            uint32_t a0 = Qu[(srow0 + gID) * 36 + d0 + tig];
            uint32_t a1 = Qu[(srow0 + gID + 8) * 36 + d0 + tig];
            uint32_t a2 = Qu[(srow0 + gID) * 36 + d0 + tig + 4];
            uint32_t a3 = Qu[(srow0 + gID + 8) * 36 + d0 + tig + 4];
#pragma unroll
            for (int nt = 0; nt < 4; ++nt) {
                int n = scol0 + nt * 8 + gID;
                uint32_t b0 = Ku[n * 36 + d0 + tig];
                uint32_t b1 = Ku[n * 36 + d0 + tig + 4];
                float* o = c + nt * 4;
                asm volatile(
                    "mma.sync.aligned.m16n8k8.row.col.f32.tf32.tf32.f32 "
                    "{%0,%1,%2,%3}, {%4,%5,%6,%7}, {%8,%9}, {%0,%1,%2,%3};"
                    : "+f"(o[0]), "+f"(o[1]), "+f"(o[2]), "+f"(o[3])
                    : "r"(a0), "r"(a1), "r"(a2), "r"(a3), "r"(b0), "r"(b1));
            }
        }

        // ---- softmax on fragments ----
        // rows r0 = srow0+gID (c0,c1), r1 = r0+8 (c2,c3)
        const int r0 = srow0 + gID, r1 = r0 + 8;
        float m0 = -1e30f, m1 = -1e30f;
#pragma unroll
        for (int nt = 0; nt < 4; ++nt) {
            m0 = fmaxf(m0, fmaxf(c[nt * 4 + 0], c[nt * 4 + 1]));
            m1 = fmaxf(m1, fmaxf(c[nt * 4 + 2], c[nt * 4 + 3]));
        }
        m0 = fmaxf(m0, __shfl_xor_sync(0xffffffffu, m0, 1));
        m0 = fmaxf(m0, __shfl_xor_sync(0xffffffffu, m0, 2));
        m1 = fmaxf(m1, __shfl_xor_sync(0xffffffffu, m1, 1));
        m1 = fmaxf(m1, __shfl_xor_sync(0xffffffffu, m1, 2));
        if (tig == 0) {
            pmx[shalf * 64 + r0] = m0;
            pmx[shalf * 64 + r1] = m1;
        }
        __syncthreads();

        float mn0 = fmaxf(mS[r0], fmaxf(pmx[r0], pmx[64 + r0]));
        float mn1 = fmaxf(mS[r1], fmaxf(pmx[r1], pmx[64 + r1]));
        float s0 = 0.0f, s1 = 0.0f;
#pragma unroll
        for (int nt = 0; nt < 4; ++nt) {
            int coln = scol0 + nt * 8 + 2 * tig;
            float p0 = __expf(c[nt * 4 + 0] - mn0);
            float p1 = __expf(c[nt * 4 + 1] - mn0);
            float p2 = __expf(c[nt * 4 + 2] - mn1);
            float p3 = __expf(c[nt * 4 + 3] - mn1);
            s0 += p0 + p1;
            s1 += p2 + p3;
            uint32_t u0 = f2tf32(p0), u1 = f2tf32(p1);
            uint32_t u2 = f2tf32(p2), u3 = f2tf32(p3);
            *(uint2*)(Ps + r0 * 68 + coln) = make_uint2(u0, u1);
            *(uint2*)(Ps + r1 * 68 + coln) = make_uint2(u2, u3);
        }
        s0 += __shfl_xor_sync(0xffffffffu, s0, 1);
        s0 += __shfl_xor_sync(0xffffffffu, s0, 2);
        s1 += __shfl_xor_sync(0xffffffffu, s1, 1);
        s1 += __shfl_xor_sync(0xffffffffu, s1, 2);
        if (tig == 0) {
            psm[shalf * 64 + r0] = s0;
            psm[shalf * 64 + r1] = s1;
        }
        __syncthreads();

        if (tid < 64) {
            int r = tid;
            float mprev = mS[r];
            float mnew = fmaxf(mprev, fmaxf(pmx[r], pmx[64 + r]));
            float alpha = __expf(mprev - mnew);
            lS[r] = lS[r] * alpha + psm[r] + psm[64 + r];
            mS[r] = mnew;
            aS[r] = alpha;
        }
        __syncthreads();

        // ---- O = O*alpha + P V  (tensor cores) ----
        float al[4];
        al[0] = aS[wr + gID];
        al[1] = aS[wr + gID + 8];
        al[2] = aS[wr + 16 + gID];
        al[3] = aS[wr + 24 + gID];
#pragma unroll
        for (int mt = 0; mt < 2; ++mt)
#pragma unroll
            for (int nt = 0; nt < 8; ++nt) {
                float* o = O + (mt * 8 + nt) * 4;
                o[0] *= al[mt * 2]; o[1] *= al[mt * 2];
                o[2] *= al[mt * 2 + 1]; o[3] *= al[mt * 2 + 1];
            }

#pragma unroll
        for (int kk = 0; kk < 8; ++kk) {
            const int j0 = kk * 8;
            uint32_t A[2][4];
#pragma unroll
            for (int mt = 0; mt < 2; ++mt) {
                int rr = wr + mt * 16 + gID;
                A[mt][0] = Pu[rr * 68 + j0 + tig];
                A[mt][1] = Pu[(rr + 8) * 68 + j0 + tig];
                A[mt][2] = Pu[rr * 68 + j0 + tig + 4];
                A[mt][3] = Pu[(rr + 8) * 68 + j0 + tig + 4];
            }
#pragma unroll
            for (int nt = 0; nt < 8; ++nt) {
                int n = wc + nt * 8 + gID;
                uint32_t B0 = Vu[(j0 + tig) * 264 + n];
                uint32_t B1 = Vu[(j0 + tig + 4) * 264 + n];
#pragma unroll
                for (int mt = 0; mt < 2; ++mt) {
                    float* o = O + (mt * 8 + nt) * 4;
                    asm volatile(
                        "mma.sync.aligned.m16n8k8.row.col.f32.tf32.tf32.f32 "
                        "{%0,%1,%2,%3}, {%4,%5,%6,%7}, {%8,%9}, {%0,%1,%2,%3};"
                        : "+f"(o[0]), "+f"(o[1]), "+f"(o[2]), "+f"(o[3])
                        : "r"(A[mt][0]), "r"(A[mt][1]), "r"(A[mt][2]), "r"(A[mt][3]),
                          "r"(B0), "r"(B1));
                }
            }
        }
    }

    // ---- normalize and write attended ----
#pragma unroll
    for (int mt = 0; mt < 2; ++mt) {
        int r0o = wr + mt * 16 + gID;
        int r1o = r0o + 8;
        float inv0 = 1.0f / lS[r0o];
        float inv1 = 1.0f / lS[r1o];
        float* d0 = g_att + ((size_t)b * NTOK + q0 + r0o) * CDIM;
        float* d1 = g_att + ((size_t)b * NTOK + q0 + r1o) * CDIM;
#pragma unroll
        for (int nt = 0; nt < 8; ++nt) {
            float* o = O + (mt * 8 + nt) * 4;
            int cc = wc + nt * 8 + tig * 2;
            *(float2*)(d0 + cc) = make_float2(o[0] * inv0, o[1] * inv0);
            *(float2*)(d1 + cc) = make_float2(o[2] * inv1, o[3] * inv1);
        }
    }
}

// ---------------------------------------------------------------------------
// Kernel 3: output projection + ReLU + residual (fp32, unchanged).
// ---------------------------------------------------------------------------
__global__ __launch_bounds__(256) void out_kernel(
    const float* __restrict__ x,
    const float* __restrict__ Wo, const float* __restrict__ bo,
    float* __restrict__ out)
{
    __shared__ float At[32 * 68];
    __shared__ float Ws[32 * 68];

    const int tid = threadIdx.x;
    const int row0 = blockIdx.x * 64;
    const int c0 = blockIdx.y * 64;
    const int sx = tid & 15, sy = tid >> 4;

    float acc[16];
#pragma unroll
    for (int i = 0; i < 16; ++i) acc[i] = 0.0f;

    for (int kc = 0; kc < 8; ++kc) {
        __syncthreads();
#pragma unroll
        for (int it = 0; it < 2; ++it) {
            int fi = tid + it * 256;
            int r = fi >> 3, quad = fi & 7;
            float4 v = *(const float4*)(g_att + (size_t)(row0 + r) * CDIM + kc * 32 + quad * 4);
            At[(quad * 4 + 0) * 68 + r] = v.x;
            At[(quad * 4 + 1) * 68 + r] = v.y;
            At[(quad * 4 + 2) * 68 + r] = v.z;
            At[(quad * 4 + 3) * 68 + r] = v.w;
        }
#pragma unroll
        for (int it = 0; it < 2; ++it) {
            int fi = tid + it * 256;
            int k = fi >> 4, g = fi & 15;
            float4 w = *(const float4*)(Wo + (size_t)(kc * 32 + k) * CDIM + c0 + g * 4);
            *(float4*)(Ws + k * 68 + g * 4) = w;
        }
        __syncthreads();
#pragma unroll
        for (int kk = 0; kk < 32; ++kk) {
            float4 a = *(const float4*)(At + kk * 68 + sy * 4);
            float4 b = *(const float4*)(Ws + kk * 68 + sx * 4);
            acc[0]  += a.x * b.x; acc[1]  += a.x * b.y; acc[2]  += a.x * b.z; acc[3]  += a.x * b.w;
            acc[4]  += a.y * b.x; acc[5]  += a.y * b.y; acc[6]  += a.y * b.z; acc[7]  += a.y * b.w;
            acc[8]  += a.z * b.x; acc[9]  += a.z * b.y; acc[10] += a.z * b.z; acc[11] += a.z * b.w;
            acc[12] += a.w * b.x; acc[13] += a.w * b.y; acc[14] += a.w * b.z; acc[15] += a.w * b.w;
        }
    }

#pragma unroll
    for (int i = 0; i < 4; ++i) {
        int row = row0 + sy * 4 + i;
#pragma unroll
        for (int j = 0; j < 4; ++j) {
            int cc = c0 + sx * 4 + j;
            float val = relu(acc[i * 4 + j] + bo[cc]);
            out[(size_t)row * CDIM + cc] = x[(size_t)row * CDIM + cc] + val;
        }
    }
}

// ---------------------------------------------------------------------------
extern "C" void kernel_launch(void* const* d_in, const int* in_sizes, int n_in,
                              void* d_out, int out_size)
{
    const float* x  = (const float*)d_in[0];
    const float* Wq = (const float*)d_in[1];
    const float* bq = (const float*)d_in[2];
    const float* Wk = (const float*)d_in[3];
    const float* bk = (const float*)d_in[4];
    const float* Wv = (const float*)d_in[5];
    const float* bv = (const float*)d_in[6];
    const float* Wo = (const float*)d_in[7];
    const float* bo = (const float*)d_in[8];
    float* out = (float*)d_out;

    cudaFuncSetAttribute(attn_kernel, cudaFuncAttributeMaxDynamicSharedMemorySize,
                         ATTN_SMEM_BYTES);

    qkv_kernel<<<dim3(256, 5), 256>>>(x, Wq, bq, Wk, bk, Wv, bv);
    attn_kernel<<<dim3(64, 4), 256, ATTN_SMEM_BYTES>>>();
    out_kernel<<<dim3(256, 4), 256>>>(x, Wo, bo, out);
}

// round 13
// speedup vs baseline: 3.1042x; 1.2835x over previous
#include <cuda_runtime.h>
#include <cuda_fp16.h>
#include <cstdint>

// Shapes: B=4, H=W=64 -> N=4096 tokens per batch, C=256, FQ=32.
#define BATCH 4
#define NTOK 4096
#define CDIM 256
#define FQ 32
#define ROWS_TOTAL (BATCH * NTOK)   // 16384

// Scratch (no allocations allowed -> __device__ globals)
__device__ float g_q[ROWS_TOTAL * FQ];
__device__ float g_k[ROWS_TOTAL * FQ];
__device__ float g_v[ROWS_TOTAL * CDIM];    // TRANSPOSED: [b][c][n] (n = token)
__device__ float g_att[ROWS_TOTAL * CDIM];

__device__ __forceinline__ float relu(float v) { return v > 0.0f ? v : 0.0f; }

__device__ __forceinline__ uint32_t pack2(float a, float b) {
    half2 h = __floats2half2_rn(a, b);   // a -> .x (low half / lower k)
    return *(uint32_t*)&h;
}

// ---------------------------------------------------------------------------
// Kernel 1: fused QKV projection (fp32 math). V is written TRANSPOSED
// per batch: g_v[b][c][n], float4 along the token dim.
// ---------------------------------------------------------------------------
__global__ __launch_bounds__(256) void qkv_kernel(
    const float* __restrict__ x,
    const float* __restrict__ Wq, const float* __restrict__ bq,
    const float* __restrict__ Wk, const float* __restrict__ bk,
    const float* __restrict__ Wv, const float* __restrict__ bv)
{
    __shared__ float Xt[32 * 68];
    __shared__ float Ws[32 * 68];

    const int tid = threadIdx.x;
    const int row0 = blockIdx.x * 64;
    const int ct = blockIdx.y;
    const int sx = tid & 15;
    const int sy = tid >> 4;

    float acc[16];
#pragma unroll
    for (int i = 0; i < 16; ++i) acc[i] = 0.0f;

    for (int kc = 0; kc < 8; ++kc) {
        __syncthreads();
#pragma unroll
        for (int it = 0; it < 2; ++it) {
            int fi = tid + it * 256;
            int r = fi >> 3, quad = fi & 7;
            float4 v = *(const float4*)(x + (size_t)(row0 + r) * CDIM + kc * 32 + quad * 4);
            Xt[(quad * 4 + 0) * 68 + r] = v.x;
            Xt[(quad * 4 + 1) * 68 + r] = v.y;
            Xt[(quad * 4 + 2) * 68 + r] = v.z;
            Xt[(quad * 4 + 3) * 68 + r] = v.w;
        }
#pragma unroll
        for (int it = 0; it < 2; ++it) {
            int fi = tid + it * 256;
            int k = fi >> 4, g = fi & 15;
            int krow = kc * 32 + k;
            float4 w;
            if (ct == 0) {
                if (g < 8) w = *(const float4*)(Wq + krow * FQ + g * 4);
                else       w = *(const float4*)(Wk + krow * FQ + (g - 8) * 4);
            } else {
                w = *(const float4*)(Wv + (size_t)krow * CDIM + (ct - 1) * 64 + g * 4);
            }
            *(float4*)(Ws + k * 68 + g * 4) = w;
        }
        __syncthreads();
#pragma unroll
        for (int kk = 0; kk < 32; ++kk) {
            float4 a = *(const float4*)(Xt + kk * 68 + sy * 4);
            float4 b = *(const float4*)(Ws + kk * 68 + sx * 4);
            acc[0]  += a.x * b.x; acc[1]  += a.x * b.y; acc[2]  += a.x * b.z; acc[3]  += a.x * b.w;
            acc[4]  += a.y * b.x; acc[5]  += a.y * b.y; acc[6]  += a.y * b.z; acc[7]  += a.y * b.w;
            acc[8]  += a.z * b.x; acc[9]  += a.z * b.y; acc[10] += a.z * b.z; acc[11] += a.z * b.w;
            acc[12] += a.w * b.x; acc[13] += a.w * b.y; acc[14] += a.w * b.z; acc[15] += a.w * b.w;
        }
    }

    if (ct == 0) {
#pragma unroll
        for (int i = 0; i < 4; ++i) {
            int row = row0 + sy * 4 + i;
#pragma unroll
            for (int j = 0; j < 4; ++j) {
                int c = sx * 4 + j;
                float val = acc[i * 4 + j];
                if (c < 32) g_q[(size_t)row * FQ + c]        = relu(val + bq[c]);
                else        g_k[(size_t)row * FQ + (c - 32)] = relu(val + bk[c - 32]);
            }
        }
    } else {
        // transposed V write: g_v[b][cc][n], n = token within batch
        const int bq_ = row0 >> 12;            // batch (4096 tokens per batch)
        const int n0 = (row0 & 4095) + sy * 4; // token base for this thread
#pragma unroll
        for (int j = 0; j < 4; ++j) {
            int cc = (ct - 1) * 64 + sx * 4 + j;
            float4 o;
            o.x = relu(acc[0 * 4 + j] + bv[cc]);
            o.y = relu(acc[1 * 4 + j] + bv[cc]);
            o.z = relu(acc[2 * 4 + j] + bv[cc]);
            o.w = relu(acc[3 * 4 + j] + bv[cc]);
            *(float4*)(g_v + ((size_t)bq_ * CDIM + cc) * NTOK + n0) = o;
        }
    }
}

// ---------------------------------------------------------------------------
// Kernel 2: flash attention, fully fp16 tensor-core (m16n8k16, fp32 accum).
// Qs/Ks: [64][40] half (frag banks 20*gID+tig, conflict-free).
// Vt:    [256][72] half (V^T: row=c, col=j; frag banks 4*gID+tig).
// Ps:    [64][72] half (frag banks 4*gID+tig).
// ---------------------------------------------------------------------------
#define H_QS 0
#define H_KS (H_QS + 64 * 40)
#define H_VT (H_KS + 64 * 40)
#define H_PS (H_VT + 256 * 72)
#define H_END (H_PS + 64 * 72)          // halves
#define F_STATS_OFF (H_END * 2)          // bytes (4-aligned: H_END even)
#define ATTN_SMEM_BYTES (F_STATS_OFF + 448 * 4)

__global__ __launch_bounds__(256, 2) void attn_kernel()
{
    extern __shared__ char smraw[];
    half* Qs = (half*)smraw + H_QS;
    half* Ks = (half*)smraw + H_KS;
    half* Vt = (half*)smraw + H_VT;
    half* Ps = (half*)smraw + H_PS;
    float* mS  = (float*)(smraw + F_STATS_OFF);
    float* lS  = mS + 64;
    float* aS  = lS + 64;
    float* pmx = aS + 64;    // [2][64]
    float* psm = pmx + 128;  // [2][64]

    const int tid = threadIdx.x;
    const int b = blockIdx.y;
    const int q0 = blockIdx.x * 64;
    const int lane = tid & 31, warp = tid >> 5;
    const int gID = lane >> 2, tig = lane & 3;
    // S-phase: warp strip 16 rows x 32 cols
    const int srow0 = (warp & 3) * 16;
    const int scol0 = (warp >> 2) * 32;
    const int shalf = warp >> 2;
    // PV-phase: warp tile 32 rows x 64 cols
    const int wr = (warp & 1) * 32;
    const int wc = (warp >> 1) * 64;

    const float* qb = g_q + (size_t)b * NTOK * FQ;
    const float* kb = g_k + (size_t)b * NTOK * FQ;
    const float* vbT = g_v + (size_t)b * CDIM * NTOK;   // [c][n]

    // Load Q tile -> Qs fp16 [r][d], stride 40
#pragma unroll
    for (int it = 0; it < 2; ++it) {
        int fi = tid + it * 256;
        int r = fi >> 3, q = fi & 7;
        float4 v = *(const float4*)(qb + (size_t)(q0 + r) * FQ + q * 4);
        uint2 t = make_uint2(pack2(v.x, v.y), pack2(v.z, v.w));
        *(uint2*)(Qs + r * 40 + q * 4) = t;
    }
    if (tid < 64) { mS[tid] = -1e30f; lS[tid] = 0.0f; }

    float O[64];
#pragma unroll
    for (int i = 0; i < 64; ++i) O[i] = 0.0f;

    for (int kt = 0; kt < 64; ++kt) {
        const int k0 = kt * 64;
        __syncthreads();   // prev PV done; Q ready (iter 0)

        // K tile -> Ks fp16 [j][d], stride 40
#pragma unroll
        for (int it = 0; it < 2; ++it) {
            int fi = tid + it * 256;
            int j = fi >> 3, q = fi & 7;
            float4 v = *(const float4*)(kb + (size_t)(k0 + j) * FQ + q * 4);
            uint2 t = make_uint2(pack2(v.x, v.y), pack2(v.z, v.w));
            *(uint2*)(Ks + j * 40 + q * 4) = t;
        }
        // V^T tile -> Vt fp16 [c][j], stride 72 (coalesced gmem rows)
#pragma unroll
        for (int it = 0; it < 16; ++it) {
            int fi = tid + it * 256;
            int c = fi >> 4, q = fi & 15;
            float4 v = *(const float4*)(vbT + (size_t)c * NTOK + k0 + q * 4);
            uint2 t = make_uint2(pack2(v.x, v.y), pack2(v.z, v.w));
            *(uint2*)(Vt + c * 72 + q * 4) = t;
        }
        __syncthreads();

        // ---- S = Q K^T (fp16 mma, fp32 accum). Warp strip 16x32. ----
        float c[16];
#pragma unroll
        for (int i = 0; i < 16; ++i) c[i] = 0.0f;
#pragma unroll
        for (int kks = 0; kks < 2; ++kks) {
            const int d0 = kks * 16;
            uint32_t a0 = *(const uint32_t*)(Qs + (srow0 + gID) * 40 + d0 + 2 * tig);
            uint32_t a1 = *(const uint32_t*)(Qs + (srow0 + gID + 8) * 40 + d0 + 2 * tig);
            uint32_t a2 = *(const uint32_t*)(Qs + (srow0 + gID) * 40 + d0 + 2 * tig + 8);
            uint32_t a3 = *(const uint32_t*)(Qs + (srow0 + gID + 8) * 40 + d0 + 2 * tig + 8);
#pragma unroll
            for (int nt = 0; nt < 4; ++nt) {
                int n = scol0 + nt * 8 + gID;
                uint32_t b0 = *(const uint32_t*)(Ks + n * 40 + d0 + 2 * tig);
                uint32_t b1 = *(const uint32_t*)(Ks + n * 40 + d0 + 2 * tig + 8);
                float* o = c + nt * 4;
                asm volatile(
                    "mma.sync.aligned.m16n8k16.row.col.f32.f16.f16.f32 "
                    "{%0,%1,%2,%3}, {%4,%5,%6,%7}, {%8,%9}, {%0,%1,%2,%3};"
                    : "+f"(o[0]), "+f"(o[1]), "+f"(o[2]), "+f"(o[3])
                    : "r"(a0), "r"(a1), "r"(a2), "r"(a3), "r"(b0), "r"(b1));
            }
        }

        // ---- softmax on fragments ----
        const int r0 = srow0 + gID, r1 = r0 + 8;
        float m0 = -1e30f, m1 = -1e30f;
#pragma unroll
        for (int nt = 0; nt < 4; ++nt) {
            m0 = fmaxf(m0, fmaxf(c[nt * 4 + 0], c[nt * 4 + 1]));
            m1 = fmaxf(m1, fmaxf(c[nt * 4 + 2], c[nt * 4 + 3]));
        }
        m0 = fmaxf(m0, __shfl_xor_sync(0xffffffffu, m0, 1));
        m0 = fmaxf(m0, __shfl_xor_sync(0xffffffffu, m0, 2));
        m1 = fmaxf(m1, __shfl_xor_sync(0xffffffffu, m1, 1));
        m1 = fmaxf(m1, __shfl_xor_sync(0xffffffffu, m1, 2));
        if (tig == 0) {
            pmx[shalf * 64 + r0] = m0;
            pmx[shalf * 64 + r1] = m1;
        }
        __syncthreads();

        float mn0 = fmaxf(mS[r0], fmaxf(pmx[r0], pmx[64 + r0]));
        float mn1 = fmaxf(mS[r1], fmaxf(pmx[r1], pmx[64 + r1]));
        float s0 = 0.0f, s1 = 0.0f;
#pragma unroll
        for (int nt = 0; nt < 4; ++nt) {
            int coln = scol0 + nt * 8 + 2 * tig;
            float p0 = __expf(c[nt * 4 + 0] - mn0);
            float p1 = __expf(c[nt * 4 + 1] - mn0);
            float p2 = __expf(c[nt * 4 + 2] - mn1);
            float p3 = __expf(c[nt * 4 + 3] - mn1);
            s0 += p0 + p1;
            s1 += p2 + p3;
            *(uint32_t*)(Ps + r0 * 72 + coln) = pack2(p0, p1);
            *(uint32_t*)(Ps + r1 * 72 + coln) = pack2(p2, p3);
        }
        s0 += __shfl_xor_sync(0xffffffffu, s0, 1);
        s0 += __shfl_xor_sync(0xffffffffu, s0, 2);
        s1 += __shfl_xor_sync(0xffffffffu, s1, 1);
        s1 += __shfl_xor_sync(0xffffffffu, s1, 2);
        if (tig == 0) {
            psm[shalf * 64 + r0] = s0;
            psm[shalf * 64 + r1] = s1;
        }
        __syncthreads();

        if (tid < 64) {
            int r = tid;
            float mprev = mS[r];
            float mnew = fmaxf(mprev, fmaxf(pmx[r], pmx[64 + r]));
            float alpha = __expf(mprev - mnew);
            lS[r] = lS[r] * alpha + psm[r] + psm[64 + r];
            mS[r] = mnew;
            aS[r] = alpha;
        }
        __syncthreads();

        // ---- O = O*alpha + P V  (fp16 mma, fp32 accum) ----
        float al[4];
        al[0] = aS[wr + gID];
        al[1] = aS[wr + gID + 8];
        al[2] = aS[wr + 16 + gID];
        al[3] = aS[wr + 24 + gID];
#pragma unroll
        for (int mt = 0; mt < 2; ++mt)
#pragma unroll
            for (int nt = 0; nt < 8; ++nt) {
                float* o = O + (mt * 8 + nt) * 4;
                o[0] *= al[mt * 2]; o[1] *= al[mt * 2];
                o[2] *= al[mt * 2 + 1]; o[3] *= al[mt * 2 + 1];
            }

#pragma unroll
        for (int kk = 0; kk < 4; ++kk) {
            const int j0 = kk * 16;
            uint32_t A[2][4];
#pragma unroll
            for (int mt = 0; mt < 2; ++mt) {
                int rr = wr + mt * 16 + gID;
                A[mt][0] = *(const uint32_t*)(Ps + rr * 72 + j0 + 2 * tig);
                A[mt][1] = *(const uint32_t*)(Ps + (rr + 8) * 72 + j0 + 2 * tig);
                A[mt][2] = *(const uint32_t*)(Ps + rr * 72 + j0 + 2 * tig + 8);
                A[mt][3] = *(const uint32_t*)(Ps + (rr + 8) * 72 + j0 + 2 * tig + 8);
            }
#pragma unroll
            for (int nt = 0; nt < 8; ++nt) {
                int n = wc + nt * 8 + gID;
                uint32_t B0 = *(const uint32_t*)(Vt + n * 72 + j0 + 2 * tig);
                uint32_t B1 = *(const uint32_t*)(Vt + n * 72 + j0 + 2 * tig + 8);
#pragma unroll
                for (int mt = 0; mt < 2; ++mt) {
                    float* o = O + (mt * 8 + nt) * 4;
                    asm volatile(
                        "mma.sync.aligned.m16n8k16.row.col.f32.f16.f16.f32 "
                        "{%0,%1,%2,%3}, {%4,%5,%6,%7}, {%8,%9}, {%0,%1,%2,%3};"
                        : "+f"(o[0]), "+f"(o[1]), "+f"(o[2]), "+f"(o[3])
                        : "r"(A[mt][0]), "r"(A[mt][1]), "r"(A[mt][2]), "r"(A[mt][3]),
                          "r"(B0), "r"(B1));
                }
            }
        }
    }

    // ---- normalize and write attended ----
#pragma unroll
    for (int mt = 0; mt < 2; ++mt) {
        int r0o = wr + mt * 16 + gID;
        int r1o = r0o + 8;
        float inv0 = 1.0f / lS[r0o];
        float inv1 = 1.0f / lS[r1o];
        float* d0 = g_att + ((size_t)b * NTOK + q0 + r0o) * CDIM;
        float* d1 = g_att + ((size_t)b * NTOK + q0 + r1o) * CDIM;
#pragma unroll
        for (int nt = 0; nt < 8; ++nt) {
            float* o = O + (mt * 8 + nt) * 4;
            int cc = wc + nt * 8 + tig * 2;
            *(float2*)(d0 + cc) = make_float2(o[0] * inv0, o[1] * inv0);
            *(float2*)(d1 + cc) = make_float2(o[2] * inv1, o[3] * inv1);
        }
    }
}

// ---------------------------------------------------------------------------
// Kernel 3: output projection + ReLU + residual (fp32, unchanged).
// ---------------------------------------------------------------------------
__global__ __launch_bounds__(256) void out_kernel(
    const float* __restrict__ x,
    const float* __restrict__ Wo, const float* __restrict__ bo,
    float* __restrict__ out)
{
    __shared__ float At[32 * 68];
    __shared__ float Ws[32 * 68];

    const int tid = threadIdx.x;
    const int row0 = blockIdx.x * 64;
    const int c0 = blockIdx.y * 64;
    const int sx = tid & 15, sy = tid >> 4;

    float acc[16];
#pragma unroll
    for (int i = 0; i < 16; ++i) acc[i] = 0.0f;

    for (int kc = 0; kc < 8; ++kc) {
        __syncthreads();
#pragma unroll
        for (int it = 0; it < 2; ++it) {
            int fi = tid + it * 256;
            int r = fi >> 3, quad = fi & 7;
            float4 v = *(const float4*)(g_att + (size_t)(row0 + r) * CDIM + kc * 32 + quad * 4);
            At[(quad * 4 + 0) * 68 + r] = v.x;
            At[(quad * 4 + 1) * 68 + r] = v.y;
            At[(quad * 4 + 2) * 68 + r] = v.z;
            At[(quad * 4 + 3) * 68 + r] = v.w;
        }
#pragma unroll
        for (int it = 0; it < 2; ++it) {
            int fi = tid + it * 256;
            int k = fi >> 4, g = fi & 15;
            float4 w = *(const float4*)(Wo + (size_t)(kc * 32 + k) * CDIM + c0 + g * 4);
            *(float4*)(Ws + k * 68 + g * 4) = w;
        }
        __syncthreads();
#pragma unroll
        for (int kk = 0; kk < 32; ++kk) {
            float4 a = *(const float4*)(At + kk * 68 + sy * 4);
            float4 b = *(const float4*)(Ws + kk * 68 + sx * 4);
            acc[0]  += a.x * b.x; acc[1]  += a.x * b.y; acc[2]  += a.x * b.z; acc[3]  += a.x * b.w;
            acc[4]  += a.y * b.x; acc[5]  += a.y * b.y; acc[6]  += a.y * b.z; acc[7]  += a.y * b.w;
            acc[8]  += a.z * b.x; acc[9]  += a.z * b.y; acc[10] += a.z * b.z; acc[11] += a.z * b.w;
            acc[12] += a.w * b.x; acc[13] += a.w * b.y; acc[14] += a.w * b.z; acc[15] += a.w * b.w;
        }
    }

#pragma unroll
    for (int i = 0; i < 4; ++i) {
        int row = row0 + sy * 4 + i;
#pragma unroll
        for (int j = 0; j < 4; ++j) {
            int cc = c0 + sx * 4 + j;
            float val = relu(acc[i * 4 + j] + bo[cc]);
            out[(size_t)row * CDIM + cc] = x[(size_t)row * CDIM + cc] + val;
        }
    }
}

// ---------------------------------------------------------------------------
extern "C" void kernel_launch(void* const* d_in, const int* in_sizes, int n_in,
                              void* d_out, int out_size)
{
    const float* x  = (const float*)d_in[0];
    const float* Wq = (const float*)d_in[1];
    const float* bq = (const float*)d_in[2];
    const float* Wk = (const float*)d_in[3];
    const float* bk = (const float*)d_in[4];
    const float* Wv = (const float*)d_in[5];
    const float* bv = (const float*)d_in[6];
    const float* Wo = (const float*)d_in[7];
    const float* bo = (const float*)d_in[8];
    float* out = (float*)d_out;

    cudaFuncSetAttribute(attn_kernel, cudaFuncAttributeMaxDynamicSharedMemorySize,
                         ATTN_SMEM_BYTES);

    qkv_kernel<<<dim3(256, 5), 256>>>(x, Wq, bq, Wk, bk, Wv, bv);
    attn_kernel<<<dim3(64, 4), 256, ATTN_SMEM_BYTES>>>();
    out_kernel<<<dim3(256, 4), 256>>>(x, Wo, bo, out);
}

// round 14
// speedup vs baseline: 4.4531x; 1.4345x over previous
#include <cuda_runtime.h>
#include <cuda_fp16.h>
#include <cstdint>

// Shapes: B=4, H=W=64 -> N=4096 tokens per batch, C=256, FQ=32.
#define BATCH 4
#define NTOK 4096
#define CDIM 256
#define FQ 32
#define ROWS_TOTAL (BATCH * NTOK)   // 16384

// Scratch (no allocations allowed -> __device__ globals)
__device__ float g_q[ROWS_TOTAL * FQ];
__device__ float g_k[ROWS_TOTAL * FQ];
__device__ float g_v[ROWS_TOTAL * CDIM];    // TRANSPOSED: [b][c][n] (n = token)
__device__ float g_att[ROWS_TOTAL * CDIM];

// Pre-transposed fp16 weights: [col][k]
__device__ half g_wqkT[64 * 256];    // cols 0-31 = Wq, 32-63 = Wk
__device__ half g_wvT[256 * 256];
__device__ half g_woT[256 * 256];

__device__ __forceinline__ float relu(float v) { return v > 0.0f ? v : 0.0f; }

__device__ __forceinline__ uint32_t pack2(float a, float b) {
    half2 h = __floats2half2_rn(a, b);   // a -> .x (low half / lower k)
    return *(uint32_t*)&h;
}

// ---------------------------------------------------------------------------
// Kernel 0: weight prep — fp32 [k][c] -> fp16 transposed [c][k].
// ---------------------------------------------------------------------------
__global__ __launch_bounds__(256) void prep_kernel(
    const float* __restrict__ Wq, const float* __restrict__ Wk,
    const float* __restrict__ Wv, const float* __restrict__ Wo)
{
    int i = blockIdx.x * 256 + threadIdx.x;   // 65536 total
    int k = i >> 8, c = i & 255;
    g_wvT[c * 256 + k] = __float2half(Wv[k * 256 + c]);
    g_woT[c * 256 + k] = __float2half(Wo[k * 256 + c]);
    if (i < 8192) {
        int kk = i >> 5, cc = i & 31;
        g_wqkT[cc * 256 + kk]        = __float2half(Wq[kk * 32 + cc]);
        g_wqkT[(cc + 32) * 256 + kk] = __float2half(Wk[kk * 32 + cc]);
    }
}

// ---------------------------------------------------------------------------
// Shared GEMM core layout constants: activation/weight tiles [64][264] half.
// Fragment banks: (4*r + tig) mod 32 -> conflict-free.
// ---------------------------------------------------------------------------
#define PROJ_SMEM_BYTES (2 * 64 * 264 * 2)

// ---------------------------------------------------------------------------
// Kernel 1: fused QKV projection, fp16 tensor cores (fp32 accum).
// grid (256, 5): ct=0 -> q|k (64 cols), ct=1..4 -> v cols. V stored transposed.
// ---------------------------------------------------------------------------
__global__ __launch_bounds__(256, 2) void qkv_kernel(
    const float* __restrict__ x,
    const float* __restrict__ bq, const float* __restrict__ bk,
    const float* __restrict__ bv)
{
    extern __shared__ char smraw[];
    half* Xs  = (half*)smraw;             // [64 r][264]
    half* Wsm = (half*)smraw + 64 * 264;  // [64 c][264]

    const int tid = threadIdx.x;
    const int lane = tid & 31, warp = tid >> 5;
    const int gID = lane >> 2, tig = lane & 3;
    const int row0 = blockIdx.x * 64;
    const int ct = blockIdx.y;
    const int wr = (warp & 3) * 16;    // warp row base
    const int wc = (warp >> 2) * 32;   // warp col base

    // Stage X tile fp32 -> fp16
#pragma unroll
    for (int it = 0; it < 16; ++it) {
        int fi = tid + it * 256;          // 4096 float4s
        int r = fi >> 6, q = fi & 63;
        float4 v = *(const float4*)(x + (size_t)(row0 + r) * CDIM + q * 4);
        uint2 t = make_uint2(pack2(v.x, v.y), pack2(v.z, v.w));
        *(uint2*)(Xs + r * 264 + q * 4) = t;
    }
    // Stage W tile (already fp16, transposed)
    const half* wsrc = (ct == 0) ? g_wqkT : (g_wvT + (size_t)(ct - 1) * 64 * 256);
#pragma unroll
    for (int it = 0; it < 8; ++it) {
        int fi = tid + it * 256;          // 2048 uint4s (8 halves each)
        int c = fi >> 5, q = fi & 31;
        uint4 t = *(const uint4*)(wsrc + (size_t)c * 256 + q * 8);
        *(uint4*)(Wsm + c * 264 + q * 8) = t;
    }
    __syncthreads();

    float acc[16];
#pragma unroll
    for (int i = 0; i < 16; ++i) acc[i] = 0.0f;

#pragma unroll
    for (int ks = 0; ks < 16; ++ks) {
        const int d0 = ks * 16;
        uint32_t a0 = *(const uint32_t*)(Xs + (wr + gID) * 264 + d0 + 2 * tig);
        uint32_t a1 = *(const uint32_t*)(Xs + (wr + gID + 8) * 264 + d0 + 2 * tig);
        uint32_t a2 = *(const uint32_t*)(Xs + (wr + gID) * 264 + d0 + 2 * tig + 8);
        uint32_t a3 = *(const uint32_t*)(Xs + (wr + gID + 8) * 264 + d0 + 2 * tig + 8);
#pragma unroll
        for (int nt = 0; nt < 4; ++nt) {
            int n = wc + nt * 8 + gID;
            uint32_t b0 = *(const uint32_t*)(Wsm + n * 264 + d0 + 2 * tig);
            uint32_t b1 = *(const uint32_t*)(Wsm + n * 264 + d0 + 2 * tig + 8);
            float* o = acc + nt * 4;
            asm volatile(
                "mma.sync.aligned.m16n8k16.row.col.f32.f16.f16.f32 "
                "{%0,%1,%2,%3}, {%4,%5,%6,%7}, {%8,%9}, {%0,%1,%2,%3};"
                : "+f"(o[0]), "+f"(o[1]), "+f"(o[2]), "+f"(o[3])
                : "r"(a0), "r"(a1), "r"(a2), "r"(a3), "r"(b0), "r"(b1));
        }
    }

    // Epilogue
    if (ct == 0) {
        int r0g = row0 + wr + gID, r1g = r0g + 8;
#pragma unroll
        for (int nt = 0; nt < 4; ++nt) {
            float* o = acc + nt * 4;
            int c = wc + nt * 8 + 2 * tig;
            if (c < 32) {
                float2 v0 = make_float2(relu(o[0] + bq[c]), relu(o[1] + bq[c + 1]));
                float2 v1 = make_float2(relu(o[2] + bq[c]), relu(o[3] + bq[c + 1]));
                *(float2*)(g_q + (size_t)r0g * FQ + c) = v0;
                *(float2*)(g_q + (size_t)r1g * FQ + c) = v1;
            } else {
                int ck = c - 32;
                float2 v0 = make_float2(relu(o[0] + bk[ck]), relu(o[1] + bk[ck + 1]));
                float2 v1 = make_float2(relu(o[2] + bk[ck]), relu(o[3] + bk[ck + 1]));
                *(float2*)(g_k + (size_t)r0g * FQ + ck) = v0;
                *(float2*)(g_k + (size_t)r1g * FQ + ck) = v1;
            }
        }
    } else {
        const int bq_ = row0 >> 12;
        const int n0 = (row0 & 4095) + wr + gID;
#pragma unroll
        for (int nt = 0; nt < 4; ++nt) {
            float* o = acc + nt * 4;
            int cc = (ct - 1) * 64 + wc + nt * 8 + 2 * tig;
            float b0v = bv[cc], b1v = bv[cc + 1];
            float* base0 = g_v + ((size_t)bq_ * CDIM + cc) * NTOK;
            float* base1 = base0 + NTOK;
            base0[n0]     = relu(o[0] + b0v);
            base1[n0]     = relu(o[1] + b1v);
            base0[n0 + 8] = relu(o[2] + b0v);
            base1[n0 + 8] = relu(o[3] + b1v);
        }
    }
}

// ---------------------------------------------------------------------------
// Kernel 2: flash attention, fully fp16 tensor-core (m16n8k16, fp32 accum).
// (unchanged from round 13)
// ---------------------------------------------------------------------------
#define H_QS 0
#define H_KS (H_QS + 64 * 40)
#define H_VT (H_KS + 64 * 40)
#define H_PS (H_VT + 256 * 72)
#define H_END (H_PS + 64 * 72)          // halves
#define F_STATS_OFF (H_END * 2)          // bytes
#define ATTN_SMEM_BYTES (F_STATS_OFF + 448 * 4)

__global__ __launch_bounds__(256, 2) void attn_kernel()
{
    extern __shared__ char smraw[];
    half* Qs = (half*)smraw + H_QS;
    half* Ks = (half*)smraw + H_KS;
    half* Vt = (half*)smraw + H_VT;
    half* Ps = (half*)smraw + H_PS;
    float* mS  = (float*)(smraw + F_STATS_OFF);
    float* lS  = mS + 64;
    float* aS  = lS + 64;
    float* pmx = aS + 64;    // [2][64]
    float* psm = pmx + 128;  // [2][64]

    const int tid = threadIdx.x;
    const int b = blockIdx.y;
    const int q0 = blockIdx.x * 64;
    const int lane = tid & 31, warp = tid >> 5;
    const int gID = lane >> 2, tig = lane & 3;
    const int srow0 = (warp & 3) * 16;
    const int scol0 = (warp >> 2) * 32;
    const int shalf = warp >> 2;
    const int wr = (warp & 1) * 32;
    const int wc = (warp >> 1) * 64;

    const float* qb = g_q + (size_t)b * NTOK * FQ;
    const float* kb = g_k + (size_t)b * NTOK * FQ;
    const float* vbT = g_v + (size_t)b * CDIM * NTOK;   // [c][n]

#pragma unroll
    for (int it = 0; it < 2; ++it) {
        int fi = tid + it * 256;
        int r = fi >> 3, q = fi & 7;
        float4 v = *(const float4*)(qb + (size_t)(q0 + r) * FQ + q * 4);
        uint2 t = make_uint2(pack2(v.x, v.y), pack2(v.z, v.w));
        *(uint2*)(Qs + r * 40 + q * 4) = t;
    }
    if (tid < 64) { mS[tid] = -1e30f; lS[tid] = 0.0f; }

    float O[64];
#pragma unroll
    for (int i = 0; i < 64; ++i) O[i] = 0.0f;

    for (int kt = 0; kt < 64; ++kt) {
        const int k0 = kt * 64;
        __syncthreads();

#pragma unroll
        for (int it = 0; it < 2; ++it) {
            int fi = tid + it * 256;
            int j = fi >> 3, q = fi & 7;
            float4 v = *(const float4*)(kb + (size_t)(k0 + j) * FQ + q * 4);
            uint2 t = make_uint2(pack2(v.x, v.y), pack2(v.z, v.w));
            *(uint2*)(Ks + j * 40 + q * 4) = t;
        }
#pragma unroll
        for (int it = 0; it < 16; ++it) {
            int fi = tid + it * 256;
            int c = fi >> 4, q = fi & 15;
            float4 v = *(const float4*)(vbT + (size_t)c * NTOK + k0 + q * 4);
            uint2 t = make_uint2(pack2(v.x, v.y), pack2(v.z, v.w));
            *(uint2*)(Vt + c * 72 + q * 4) = t;
        }
        __syncthreads();

        float c[16];
#pragma unroll
        for (int i = 0; i < 16; ++i) c[i] = 0.0f;
#pragma unroll
        for (int kks = 0; kks < 2; ++kks) {
            const int d0 = kks * 16;
            uint32_t a0 = *(const uint32_t*)(Qs + (srow0 + gID) * 40 + d0 + 2 * tig);
            uint32_t a1 = *(const uint32_t*)(Qs + (srow0 + gID + 8) * 40 + d0 + 2 * tig);
            uint32_t a2 = *(const uint32_t*)(Qs + (srow0 + gID) * 40 + d0 + 2 * tig + 8);
            uint32_t a3 = *(const uint32_t*)(Qs + (srow0 + gID + 8) * 40 + d0 + 2 * tig + 8);
#pragma unroll
            for (int nt = 0; nt < 4; ++nt) {
                int n = scol0 + nt * 8 + gID;
                uint32_t b0 = *(const uint32_t*)(Ks + n * 40 + d0 + 2 * tig);
                uint32_t b1 = *(const uint32_t*)(Ks + n * 40 + d0 + 2 * tig + 8);
                float* o = c + nt * 4;
                asm volatile(
                    "mma.sync.aligned.m16n8k16.row.col.f32.f16.f16.f32 "
                    "{%0,%1,%2,%3}, {%4,%5,%6,%7}, {%8,%9}, {%0,%1,%2,%3};"
                    : "+f"(o[0]), "+f"(o[1]), "+f"(o[2]), "+f"(o[3])
                    : "r"(a0), "r"(a1), "r"(a2), "r"(a3), "r"(b0), "r"(b1));
            }
        }

        const int r0 = srow0 + gID, r1 = r0 + 8;
        float m0 = -1e30f, m1 = -1e30f;
#pragma unroll
        for (int nt = 0; nt < 4; ++nt) {
            m0 = fmaxf(m0, fmaxf(c[nt * 4 + 0], c[nt * 4 + 1]));
            m1 = fmaxf(m1, fmaxf(c[nt * 4 + 2], c[nt * 4 + 3]));
        }
        m0 = fmaxf(m0, __shfl_xor_sync(0xffffffffu, m0, 1));
        m0 = fmaxf(m0, __shfl_xor_sync(0xffffffffu, m0, 2));
        m1 = fmaxf(m1, __shfl_xor_sync(0xffffffffu, m1, 1));
        m1 = fmaxf(m1, __shfl_xor_sync(0xffffffffu, m1, 2));
        if (tig == 0) {
            pmx[shalf * 64 + r0] = m0;
            pmx[shalf * 64 + r1] = m1;
        }
        __syncthreads();

        float mn0 = fmaxf(mS[r0], fmaxf(pmx[r0], pmx[64 + r0]));
        float mn1 = fmaxf(mS[r1], fmaxf(pmx[r1], pmx[64 + r1]));
        float s0 = 0.0f, s1 = 0.0f;
#pragma unroll
        for (int nt = 0; nt < 4; ++nt) {
            int coln = scol0 + nt * 8 + 2 * tig;
            float p0 = __expf(c[nt * 4 + 0] - mn0);
            float p1 = __expf(c[nt * 4 + 1] - mn0);
            float p2 = __expf(c[nt * 4 + 2] - mn1);
            float p3 = __expf(c[nt * 4 + 3] - mn1);
            s0 += p0 + p1;
            s1 += p2 + p3;
            *(uint32_t*)(Ps + r0 * 72 + coln) = pack2(p0, p1);
            *(uint32_t*)(Ps + r1 * 72 + coln) = pack2(p2, p3);
        }
        s0 += __shfl_xor_sync(0xffffffffu, s0, 1);
        s0 += __shfl_xor_sync(0xffffffffu, s0, 2);
        s1 += __shfl_xor_sync(0xffffffffu, s1, 1);
        s1 += __shfl_xor_sync(0xffffffffu, s1, 2);
        if (tig == 0) {
            psm[shalf * 64 + r0] = s0;
            psm[shalf * 64 + r1] = s1;
        }
        __syncthreads();

        if (tid < 64) {
            int r = tid;
            float mprev = mS[r];
            float mnew = fmaxf(mprev, fmaxf(pmx[r], pmx[64 + r]));
            float alpha = __expf(mprev - mnew);
            lS[r] = lS[r] * alpha + psm[r] + psm[64 + r];
            mS[r] = mnew;
            aS[r] = alpha;
        }
        __syncthreads();

        float al[4];
        al[0] = aS[wr + gID];
        al[1] = aS[wr + gID + 8];
        al[2] = aS[wr + 16 + gID];
        al[3] = aS[wr + 24 + gID];
#pragma unroll
        for (int mt = 0; mt < 2; ++mt)
#pragma unroll
            for (int nt = 0; nt < 8; ++nt) {
                float* o = O + (mt * 8 + nt) * 4;
                o[0] *= al[mt * 2]; o[1] *= al[mt * 2];
                o[2] *= al[mt * 2 + 1]; o[3] *= al[mt * 2 + 1];
            }

#pragma unroll
        for (int kk = 0; kk < 4; ++kk) {
            const int j0 = kk * 16;
            uint32_t A[2][4];
#pragma unroll
            for (int mt = 0; mt < 2; ++mt) {
                int rr = wr + mt * 16 + gID;
                A[mt][0] = *(const uint32_t*)(Ps + rr * 72 + j0 + 2 * tig);
                A[mt][1] = *(const uint32_t*)(Ps + (rr + 8) * 72 + j0 + 2 * tig);
                A[mt][2] = *(const uint32_t*)(Ps + rr * 72 + j0 + 2 * tig + 8);
                A[mt][3] = *(const uint32_t*)(Ps + (rr + 8) * 72 + j0 + 2 * tig + 8);
            }
#pragma unroll
            for (int nt = 0; nt < 8; ++nt) {
                int n = wc + nt * 8 + gID;
                uint32_t B0 = *(const uint32_t*)(Vt + n * 72 + j0 + 2 * tig);
                uint32_t B1 = *(const uint32_t*)(Vt + n * 72 + j0 + 2 * tig + 8);
#pragma unroll
                for (int mt = 0; mt < 2; ++mt) {
                    float* o = O + (mt * 8 + nt) * 4;
                    asm volatile(
                        "mma.sync.aligned.m16n8k16.row.col.f32.f16.f16.f32 "
                        "{%0,%1,%2,%3}, {%4,%5,%6,%7}, {%8,%9}, {%0,%1,%2,%3};"
                        : "+f"(o[0]), "+f"(o[1]), "+f"(o[2]), "+f"(o[3])
                        : "r"(A[mt][0]), "r"(A[mt][1]), "r"(A[mt][2]), "r"(A[mt][3]),
                          "r"(B0), "r"(B1));
                }
            }
        }
    }

#pragma unroll
    for (int mt = 0; mt < 2; ++mt) {
        int r0o = wr + mt * 16 + gID;
        int r1o = r0o + 8;
        float inv0 = 1.0f / lS[r0o];
        float inv1 = 1.0f / lS[r1o];
        float* d0 = g_att + ((size_t)b * NTOK + q0 + r0o) * CDIM;
        float* d1 = g_att + ((size_t)b * NTOK + q0 + r1o) * CDIM;
#pragma unroll
        for (int nt = 0; nt < 8; ++nt) {
            float* o = O + (mt * 8 + nt) * 4;
            int cc = wc + nt * 8 + tig * 2;
            *(float2*)(d0 + cc) = make_float2(o[0] * inv0, o[1] * inv0);
            *(float2*)(d1 + cc) = make_float2(o[2] * inv1, o[3] * inv1);
        }
    }
}

// ---------------------------------------------------------------------------
// Kernel 3: output projection + ReLU + residual, fp16 tensor cores.
// grid (256, 4).
// ---------------------------------------------------------------------------
__global__ __launch_bounds__(256, 2) void out_kernel(
    const float* __restrict__ x,
    const float* __restrict__ bo,
    float* __restrict__ out)
{
    extern __shared__ char smraw[];
    half* Xs  = (half*)smraw;
    half* Wsm = (half*)smraw + 64 * 264;

    const int tid = threadIdx.x;
    const int lane = tid & 31, warp = tid >> 5;
    const int gID = lane >> 2, tig = lane & 3;
    const int row0 = blockIdx.x * 64;
    const int c0 = blockIdx.y * 64;
    const int wr = (warp & 3) * 16;
    const int wc = (warp >> 2) * 32;

#pragma unroll
    for (int it = 0; it < 16; ++it) {
        int fi = tid + it * 256;
        int r = fi >> 6, q = fi & 63;
        float4 v = *(const float4*)(g_att + (size_t)(row0 + r) * CDIM + q * 4);
        uint2 t = make_uint2(pack2(v.x, v.y), pack2(v.z, v.w));
        *(uint2*)(Xs + r * 264 + q * 4) = t;
    }
    const half* wsrc = g_woT + (size_t)c0 * 256;
#pragma unroll
    for (int it = 0; it < 8; ++it) {
        int fi = tid + it * 256;
        int c = fi >> 5, q = fi & 31;
        uint4 t = *(const uint4*)(wsrc + (size_t)c * 256 + q * 8);
        *(uint4*)(Wsm + c * 264 + q * 8) = t;
    }
    __syncthreads();

    float acc[16];
#pragma unroll
    for (int i = 0; i < 16; ++i) acc[i] = 0.0f;

#pragma unroll
    for (int ks = 0; ks < 16; ++ks) {
        const int d0 = ks * 16;
        uint32_t a0 = *(const uint32_t*)(Xs + (wr + gID) * 264 + d0 + 2 * tig);
        uint32_t a1 = *(const uint32_t*)(Xs + (wr + gID + 8) * 264 + d0 + 2 * tig);
        uint32_t a2 = *(const uint32_t*)(Xs + (wr + gID) * 264 + d0 + 2 * tig + 8);
        uint32_t a3 = *(const uint32_t*)(Xs + (wr + gID + 8) * 264 + d0 + 2 * tig + 8);
#pragma unroll
        for (int nt = 0; nt < 4; ++nt) {
            int n = wc + nt * 8 + gID;
            uint32_t b0 = *(const uint32_t*)(Wsm + n * 264 + d0 + 2 * tig);
            uint32_t b1 = *(const uint32_t*)(Wsm + n * 264 + d0 + 2 * tig + 8);
            float* o = acc + nt * 4;
            asm volatile(
                "mma.sync.aligned.m16n8k16.row.col.f32.f16.f16.f32 "
                "{%0,%1,%2,%3}, {%4,%5,%6,%7}, {%8,%9}, {%0,%1,%2,%3};"
                : "+f"(o[0]), "+f"(o[1]), "+f"(o[2]), "+f"(o[3])
                : "r"(a0), "r"(a1), "r"(a2), "r"(a3), "r"(b0), "r"(b1));
        }
    }

    int r0g = row0 + wr + gID, r1g = r0g + 8;
#pragma unroll
    for (int nt = 0; nt < 4; ++nt) {
        float* o = acc + nt * 4;
        int cc = c0 + wc + nt * 8 + 2 * tig;
        float b0v = bo[cc], b1v = bo[cc + 1];
        float2 x0 = *(const float2*)(x + (size_t)r0g * CDIM + cc);
        float2 x1 = *(const float2*)(x + (size_t)r1g * CDIM + cc);
        float2 v0 = make_float2(x0.x + relu(o[0] + b0v), x0.y + relu(o[1] + b1v));
        float2 v1 = make_float2(x1.x + relu(o[2] + b0v), x1.y + relu(o[3] + b1v));
        *(float2*)(out + (size_t)r0g * CDIM + cc) = v0;
        *(float2*)(out + (size_t)r1g * CDIM + cc) = v1;
    }
}

// ---------------------------------------------------------------------------
extern "C" void kernel_launch(void* const* d_in, const int* in_sizes, int n_in,
                              void* d_out, int out_size)
{
    const float* x  = (const float*)d_in[0];
    const float* Wq = (const float*)d_in[1];
    const float* bq = (const float*)d_in[2];
    const float* Wk = (const float*)d_in[3];
    const float* bk = (const float*)d_in[4];
    const float* Wv = (const float*)d_in[5];
    const float* bv = (const float*)d_in[6];
    const float* Wo = (const float*)d_in[7];
    const float* bo = (const float*)d_in[8];
    float* out = (float*)d_out;

    cudaFuncSetAttribute(attn_kernel, cudaFuncAttributeMaxDynamicSharedMemorySize,
                         ATTN_SMEM_BYTES);
    cudaFuncSetAttribute(qkv_kernel, cudaFuncAttributeMaxDynamicSharedMemorySize,
                         PROJ_SMEM_BYTES);
    cudaFuncSetAttribute(out_kernel, cudaFuncAttributeMaxDynamicSharedMemorySize,
                         PROJ_SMEM_BYTES);

    prep_kernel<<<256, 256>>>(Wq, Wk, Wv, Wo);
    qkv_kernel<<<dim3(256, 5), 256, PROJ_SMEM_BYTES>>>(x, bq, bk, bv);
    attn_kernel<<<dim3(64, 4), 256, ATTN_SMEM_BYTES>>>();
    out_kernel<<<dim3(256, 4), 256, PROJ_SMEM_BYTES>>>(x, bo, out);
}

// round 16
// speedup vs baseline: 4.9281x; 1.1067x over previous
#include <cuda_runtime.h>
#include <cuda_fp16.h>
#include <cstdint>

// Shapes: B=4, H=W=64 -> N=4096 tokens per batch, C=256, FQ=32.
#define BATCH 4
#define NTOK 4096
#define CDIM 256
#define FQ 32
#define ROWS_TOTAL (BATCH * NTOK)   // 16384

// Scratch (no allocations allowed -> __device__ globals)
__device__ half g_qh[ROWS_TOTAL * FQ];     // [row][32] fp16
__device__ half g_kh[ROWS_TOTAL * FQ];     // [row][32] fp16
__device__ half g_vh[ROWS_TOTAL * CDIM];   // TRANSPOSED: [b][c][n] fp16
__device__ half g_atth[ROWS_TOTAL * CDIM]; // attended, fp16

// Pre-transposed fp16 weights: [col][k]
__device__ half g_wqkT[64 * 256];    // cols 0-31 = Wq, 32-63 = Wk
__device__ half g_wvT[256 * 256];
__device__ half g_woT[256 * 256];

__device__ __forceinline__ float relu(float v) { return v > 0.0f ? v : 0.0f; }

__device__ __forceinline__ uint32_t pack2(float a, float b) {
    half2 h = __floats2half2_rn(a, b);   // a -> .x (lower k)
    return *(uint32_t*)&h;
}

// ---------------------------------------------------------------------------
// Kernel 0: weight prep — fp32 [k][c] -> fp16 transposed [c][k].
// ---------------------------------------------------------------------------
__global__ __launch_bounds__(256) void prep_kernel(
    const float* __restrict__ Wq, const float* __restrict__ Wk,
    const float* __restrict__ Wv, const float* __restrict__ Wo)
{
    int i = blockIdx.x * 256 + threadIdx.x;   // 65536 total
    int k = i >> 8, c = i & 255;
    g_wvT[c * 256 + k] = __float2half(Wv[k * 256 + c]);
    g_woT[c * 256 + k] = __float2half(Wo[k * 256 + c]);
    if (i < 8192) {
        int kk = i >> 5, cc = i & 31;
        g_wqkT[cc * 256 + kk]        = __float2half(Wq[kk * 32 + cc]);
        g_wqkT[(cc + 32) * 256 + kk] = __float2half(Wk[kk * 32 + cc]);
    }
}

#define PROJ_SMEM_BYTES (2 * 64 * 264 * 2)

// ---------------------------------------------------------------------------
// Kernel 1: fused QKV projection, fp16 mma (fp32 accum). Outputs fp16.
// grid (256, 5): ct=0 -> q|k, ct=1..4 -> v cols. V stored transposed [b][c][n].
// ---------------------------------------------------------------------------
__global__ __launch_bounds__(256, 2) void qkv_kernel(
    const float* __restrict__ x,
    const float* __restrict__ bq, const float* __restrict__ bk,
    const float* __restrict__ bv)
{
    extern __shared__ char smraw[];
    half* Xs  = (half*)smraw;             // [64 r][264]
    half* Wsm = (half*)smraw + 64 * 264;  // [64 c][264]

    const int tid = threadIdx.x;
    const int lane = tid & 31, warp = tid >> 5;
    const int gID = lane >> 2, tig = lane & 3;
    const int row0 = blockIdx.x * 64;
    const int ct = blockIdx.y;
    const int wr = (warp & 3) * 16;
    const int wc = (warp >> 2) * 32;

#pragma unroll
    for (int it = 0; it < 16; ++it) {
        int fi = tid + it * 256;
        int r = fi >> 6, q = fi & 63;
        float4 v = *(const float4*)(x + (size_t)(row0 + r) * CDIM + q * 4);
        uint2 t = make_uint2(pack2(v.x, v.y), pack2(v.z, v.w));
        *(uint2*)(Xs + r * 264 + q * 4) = t;
    }
    const half* wsrc = (ct == 0) ? g_wqkT : (g_wvT + (size_t)(ct - 1) * 64 * 256);
#pragma unroll
    for (int it = 0; it < 8; ++it) {
        int fi = tid + it * 256;
        int c = fi >> 5, q = fi & 31;
        uint4 t = *(const uint4*)(wsrc + (size_t)c * 256 + q * 8);
        *(uint4*)(Wsm + c * 264 + q * 8) = t;
    }
    __syncthreads();

    float acc[16];
#pragma unroll
    for (int i = 0; i < 16; ++i) acc[i] = 0.0f;

#pragma unroll
    for (int ks = 0; ks < 16; ++ks) {
        const int d0 = ks * 16;
        uint32_t a0 = *(const uint32_t*)(Xs + (wr + gID) * 264 + d0 + 2 * tig);
        uint32_t a1 = *(const uint32_t*)(Xs + (wr + gID + 8) * 264 + d0 + 2 * tig);
        uint32_t a2 = *(const uint32_t*)(Xs + (wr + gID) * 264 + d0 + 2 * tig + 8);
        uint32_t a3 = *(const uint32_t*)(Xs + (wr + gID + 8) * 264 + d0 + 2 * tig + 8);
#pragma unroll
        for (int nt = 0; nt < 4; ++nt) {
            int n = wc + nt * 8 + gID;
            uint32_t b0 = *(const uint32_t*)(Wsm + n * 264 + d0 + 2 * tig);
            uint32_t b1 = *(const uint32_t*)(Wsm + n * 264 + d0 + 2 * tig + 8);
            float* o = acc + nt * 4;
            asm volatile(
                "mma.sync.aligned.m16n8k16.row.col.f32.f16.f16.f32 "
                "{%0,%1,%2,%3}, {%4,%5,%6,%7}, {%8,%9}, {%0,%1,%2,%3};"
                : "+f"(o[0]), "+f"(o[1]), "+f"(o[2]), "+f"(o[3])
                : "r"(a0), "r"(a1), "r"(a2), "r"(a3), "r"(b0), "r"(b1));
        }
    }

    if (ct == 0) {
        int r0g = row0 + wr + gID, r1g = r0g + 8;
#pragma unroll
        for (int nt = 0; nt < 4; ++nt) {
            float* o = acc + nt * 4;
            int c = wc + nt * 8 + 2 * tig;
            if (c < 32) {
                *(uint32_t*)(g_qh + (size_t)r0g * FQ + c) =
                    pack2(relu(o[0] + bq[c]), relu(o[1] + bq[c + 1]));
                *(uint32_t*)(g_qh + (size_t)r1g * FQ + c) =
                    pack2(relu(o[2] + bq[c]), relu(o[3] + bq[c + 1]));
            } else {
                int ck = c - 32;
                *(uint32_t*)(g_kh + (size_t)r0g * FQ + ck) =
                    pack2(relu(o[0] + bk[ck]), relu(o[1] + bk[ck + 1]));
                *(uint32_t*)(g_kh + (size_t)r1g * FQ + ck) =
                    pack2(relu(o[2] + bk[ck]), relu(o[3] + bk[ck + 1]));
            }
        }
    } else {
        const int bq_ = row0 >> 12;
        const int n0 = (row0 & 4095) + wr + gID;
#pragma unroll
        for (int nt = 0; nt < 4; ++nt) {
            float* o = acc + nt * 4;
            int cc = (ct - 1) * 64 + wc + nt * 8 + 2 * tig;
            float b0v = bv[cc], b1v = bv[cc + 1];
            half* base0 = g_vh + ((size_t)bq_ * CDIM + cc) * NTOK;
            half* base1 = base0 + NTOK;
            base0[n0]     = __float2half(relu(o[0] + b0v));
            base1[n0]     = __float2half(relu(o[1] + b1v));
            base0[n0 + 8] = __float2half(relu(o[2] + b0v));
            base1[n0 + 8] = __float2half(relu(o[3] + b1v));
        }
    }
}

// ---------------------------------------------------------------------------
// Kernel 2: flash attention, fp16 HMMA (m16n8k16, fp32 accum), fp16 I/O.
// Qs/Ks: [64][40] half; Vt: [256][72] half (V^T); Ps: [64][72] half.
// All fragment LDS conflict-free (banks 20g+t / 4g+t patterns).
// ---------------------------------------------------------------------------
#define H_QS 0
#define H_KS (H_QS + 64 * 40)
#define H_VT (H_KS + 64 * 40)
#define H_PS (H_VT + 256 * 72)
#define H_END (H_PS + 64 * 72)          // halves
#define F_STATS_OFF (H_END * 2)          // bytes
#define ATTN_SMEM_BYTES (F_STATS_OFF + 448 * 4)

__global__ __launch_bounds__(256, 2) void attn_kernel()
{
    extern __shared__ char smraw[];
    half* Qs = (half*)smraw + H_QS;
    half* Ks = (half*)smraw + H_KS;
    half* Vt = (half*)smraw + H_VT;
    half* Ps = (half*)smraw + H_PS;
    float* mS  = (float*)(smraw + F_STATS_OFF);
    float* lS  = mS + 64;
    float* aS  = lS + 64;
    float* pmx = aS + 64;    // [2][64]
    float* psm = pmx + 128;  // [2][64]

    const int tid = threadIdx.x;
    const int b = blockIdx.y;
    const int q0 = blockIdx.x * 64;
    const int lane = tid & 31, warp = tid >> 5;
    const int gID = lane >> 2, tig = lane & 3;
    const int srow0 = (warp & 3) * 16;
    const int scol0 = (warp >> 2) * 32;
    const int shalf = warp >> 2;
    const int wr = (warp & 1) * 32;
    const int wc = (warp >> 1) * 64;

    const half* qh = g_qh + (size_t)b * NTOK * FQ;
    const half* kh = g_kh + (size_t)b * NTOK * FQ;
    const half* vh = g_vh + (size_t)b * CDIM * NTOK;   // [c][n]

    // Stage Q: 64 rows x 32 halves = 256 uint4 chunks
    {
        int r = tid >> 2, qo = tid & 3;
        uint4 v = *(const uint4*)(qh + (size_t)(q0 + r) * FQ + qo * 8);
        *(uint4*)(Qs + r * 40 + qo * 8) = v;
    }
    if (tid < 64) { mS[tid] = -1e30f; lS[tid] = 0.0f; }

    float O[64];
#pragma unroll
    for (int i = 0; i < 64; ++i) O[i] = 0.0f;

    for (int kt = 0; kt < 64; ++kt) {
        const int k0 = kt * 64;
        __syncthreads();

        // K tile: 256 uint4 chunks
        {
            int j = tid >> 2, qo = tid & 3;
            uint4 v = *(const uint4*)(kh + (size_t)(k0 + j) * FQ + qo * 8);
            *(uint4*)(Ks + j * 40 + qo * 8) = v;
        }
        // V^T tile: [256 c][64 j] halves = 2048 uint4 chunks
#pragma unroll
        for (int it = 0; it < 8; ++it) {
            int fi = tid + it * 256;
            int c = fi >> 3, q = fi & 7;
            uint4 v = *(const uint4*)(vh + (size_t)c * NTOK + k0 + q * 8);
            *(uint4*)(Vt + c * 72 + q * 8) = v;
        }
        __syncthreads();

        // ---- S = Q K^T. Warp strip 16x32. ----
        float c[16];
#pragma unroll
        for (int i = 0; i < 16; ++i) c[i] = 0.0f;
#pragma unroll
        for (int kks = 0; kks < 2; ++kks) {
            const int d0 = kks * 16;
            uint32_t a0 = *(const uint32_t*)(Qs + (srow0 + gID) * 40 + d0 + 2 * tig);
            uint32_t a1 = *(const uint32_t*)(Qs + (srow0 + gID + 8) * 40 + d0 + 2 * tig);
            uint32_t a2 = *(const uint32_t*)(Qs + (srow0 + gID) * 40 + d0 + 2 * tig + 8);
            uint32_t a3 = *(const uint32_t*)(Qs + (srow0 + gID + 8) * 40 + d0 + 2 * tig + 8);
#pragma unroll
            for (int nt = 0; nt < 4; ++nt) {
                int n = scol0 + nt * 8 + gID;
                uint32_t b0 = *(const uint32_t*)(Ks + n * 40 + d0 + 2 * tig);
                uint32_t b1 = *(const uint32_t*)(Ks + n * 40 + d0 + 2 * tig + 8);
                float* o = c + nt * 4;
                asm volatile(
                    "mma.sync.aligned.m16n8k16.row.col.f32.f16.f16.f32 "
                    "{%0,%1,%2,%3}, {%4,%5,%6,%7}, {%8,%9}, {%0,%1,%2,%3};"
                    : "+f"(o[0]), "+f"(o[1]), "+f"(o[2]), "+f"(o[3])
                    : "r"(a0), "r"(a1), "r"(a2), "r"(a3), "r"(b0), "r"(b1));
            }
        }

        // ---- online softmax ----
        const int r0 = srow0 + gID, r1 = r0 + 8;
        float m0 = -1e30f, m1 = -1e30f;
#pragma unroll
        for (int nt = 0; nt < 4; ++nt) {
            m0 = fmaxf(m0, fmaxf(c[nt * 4 + 0], c[nt * 4 + 1]));
            m1 = fmaxf(m1, fmaxf(c[nt * 4 + 2], c[nt * 4 + 3]));
        }
        m0 = fmaxf(m0, __shfl_xor_sync(0xffffffffu, m0, 1));
        m0 = fmaxf(m0, __shfl_xor_sync(0xffffffffu, m0, 2));
        m1 = fmaxf(m1, __shfl_xor_sync(0xffffffffu, m1, 1));
        m1 = fmaxf(m1, __shfl_xor_sync(0xffffffffu, m1, 2));
        if (tig == 0) {
            pmx[shalf * 64 + r0] = m0;
            pmx[shalf * 64 + r1] = m1;
        }
        __syncthreads();

        float mn0 = fmaxf(mS[r0], fmaxf(pmx[r0], pmx[64 + r0]));
        float mn1 = fmaxf(mS[r1], fmaxf(pmx[r1], pmx[64 + r1]));
        float s0 = 0.0f, s1 = 0.0f;
#pragma unroll
        for (int nt = 0; nt < 4; ++nt) {
            int coln = scol0 + nt * 8 + 2 * tig;
            float p0 = __expf(c[nt * 4 + 0] - mn0);
            float p1 = __expf(c[nt * 4 + 1] - mn0);
            float p2 = __expf(c[nt * 4 + 2] - mn1);
            float p3 = __expf(c[nt * 4 + 3] - mn1);
            s0 += p0 + p1;
            s1 += p2 + p3;
            *(uint32_t*)(Ps + r0 * 72 + coln) = pack2(p0, p1);
            *(uint32_t*)(Ps + r1 * 72 + coln) = pack2(p2, p3);
        }
        s0 += __shfl_xor_sync(0xffffffffu, s0, 1);
        s0 += __shfl_xor_sync(0xffffffffu, s0, 2);
        s1 += __shfl_xor_sync(0xffffffffu, s1, 1);
        s1 += __shfl_xor_sync(0xffffffffu, s1, 2);
        if (tig == 0) {
            psm[shalf * 64 + r0] = s0;
            psm[shalf * 64 + r1] = s1;
        }
        __syncthreads();

        if (tid < 64) {
            int r = tid;
            float mprev = mS[r];
            float mnew = fmaxf(mprev, fmaxf(pmx[r], pmx[64 + r]));
            float alpha = __expf(mprev - mnew);
            lS[r] = lS[r] * alpha + psm[r] + psm[64 + r];
            mS[r] = mnew;
            aS[r] = alpha;
        }
        __syncthreads();

        // ---- O = O*alpha + P V ----
        float al[4];
        al[0] = aS[wr + gID];
        al[1] = aS[wr + gID + 8];
        al[2] = aS[wr + 16 + gID];
        al[3] = aS[wr + 24 + gID];
#pragma unroll
        for (int mt = 0; mt < 2; ++mt)
#pragma unroll
            for (int nt = 0; nt < 8; ++nt) {
                float* o = O + (mt * 8 + nt) * 4;
                o[0] *= al[mt * 2]; o[1] *= al[mt * 2];
                o[2] *= al[mt * 2 + 1]; o[3] *= al[mt * 2 + 1];
            }

#pragma unroll
        for (int kk = 0; kk < 4; ++kk) {
            const int j0 = kk * 16;
            uint32_t A[2][4];
#pragma unroll
            for (int mt = 0; mt < 2; ++mt) {
                int rr = wr + mt * 16 + gID;
                A[mt][0] = *(const uint32_t*)(Ps + rr * 72 + j0 + 2 * tig);
                A[mt][1] = *(const uint32_t*)(Ps + (rr + 8) * 72 + j0 + 2 * tig);
                A[mt][2] = *(const uint32_t*)(Ps + rr * 72 + j0 + 2 * tig + 8);
                A[mt][3] = *(const uint32_t*)(Ps + (rr + 8) * 72 + j0 + 2 * tig + 8);
            }
#pragma unroll
            for (int nt = 0; nt < 8; ++nt) {
                int n = wc + nt * 8 + gID;
                uint32_t B0 = *(const uint32_t*)(Vt + n * 72 + j0 + 2 * tig);
                uint32_t B1 = *(const uint32_t*)(Vt + n * 72 + j0 + 2 * tig + 8);
#pragma unroll
                for (int mt = 0; mt < 2; ++mt) {
                    float* o = O + (mt * 8 + nt) * 4;
                    asm volatile(
                        "mma.sync.aligned.m16n8k16.row.col.f32.f16.f16.f32 "
                        "{%0,%1,%2,%3}, {%4,%5,%6,%7}, {%8,%9}, {%0,%1,%2,%3};"
                        : "+f"(o[0]), "+f"(o[1]), "+f"(o[2]), "+f"(o[3])
                        : "r"(A[mt][0]), "r"(A[mt][1]), "r"(A[mt][2]), "r"(A[mt][3]),
                          "r"(B0), "r"(B1));
                }
            }
        }
    }

    // ---- normalize and write attended (fp16) ----
#pragma unroll
    for (int mt = 0; mt < 2; ++mt) {
        int r0o = wr + mt * 16 + gID;
        int r1o = r0o + 8;
        float inv0 = 1.0f / lS[r0o];
        float inv1 = 1.0f / lS[r1o];
        half* d0 = g_atth + ((size_t)b * NTOK + q0 + r0o) * CDIM;
        half* d1 = g_atth + ((size_t)b * NTOK + q0 + r1o) * CDIM;
#pragma unroll
        for (int nt = 0; nt < 8; ++nt) {
            float* o = O + (mt * 8 + nt) * 4;
            int cc = wc + nt * 8 + tig * 2;
            *(uint32_t*)(d0 + cc) = pack2(o[0] * inv0, o[1] * inv0);
            *(uint32_t*)(d1 + cc) = pack2(o[2] * inv1, o[3] * inv1);
        }
    }
}

// ---------------------------------------------------------------------------
// Kernel 3: output projection + ReLU + residual, fp16 mma, fp16 input.
// ---------------------------------------------------------------------------
__global__ __launch_bounds__(256, 2) void out_kernel(
    const float* __restrict__ x,
    const float* __restrict__ bo,
    float* __restrict__ out)
{
    extern __shared__ char smraw[];
    half* Xs  = (half*)smraw;
    half* Wsm = (half*)smraw + 64 * 264;

    const int tid = threadIdx.x;
    const int lane = tid & 31, warp = tid >> 5;
    const int gID = lane >> 2, tig = lane & 3;
    const int row0 = blockIdx.x * 64;
    const int c0 = blockIdx.y * 64;
    const int wr = (warp & 3) * 16;
    const int wc = (warp >> 2) * 32;

    // Stage attended (already fp16): 64 rows x 256 halves = 2048 uint4
#pragma unroll
    for (int it = 0; it < 8; ++it) {
        int fi = tid + it * 256;
        int r = fi >> 5, q = fi & 31;
        uint4 v = *(const uint4*)(g_atth + (size_t)(row0 + r) * CDIM + q * 8);
        *(uint4*)(Xs + r * 264 + q * 8) = v;
    }
    const half* wsrc = g_woT + (size_t)c0 * 256;
#pragma unroll
    for (int it = 0; it < 8; ++it) {
        int fi = tid + it * 256;
        int c = fi >> 5, q = fi & 31;
        uint4 t = *(const uint4*)(wsrc + (size_t)c * 256 + q * 8);
        *(uint4*)(Wsm + c * 264 + q * 8) = t;
    }
    __syncthreads();

    float acc[16];
#pragma unroll
    for (int i = 0; i < 16; ++i) acc[i] = 0.0f;

#pragma unroll
    for (int ks = 0; ks < 16; ++ks) {
        const int d0 = ks * 16;
        uint32_t a0 = *(const uint32_t*)(Xs + (wr + gID) * 264 + d0 + 2 * tig);
        uint32_t a1 = *(const uint32_t*)(Xs + (wr + gID + 8) * 264 + d0 + 2 * tig);
        uint32_t a2 = *(const uint32_t*)(Xs + (wr + gID) * 264 + d0 + 2 * tig + 8);
        uint32_t a3 = *(const uint32_t*)(Xs + (wr + gID + 8) * 264 + d0 + 2 * tig + 8);
#pragma unroll
        for (int nt = 0; nt < 4; ++nt) {
            int n = wc + nt * 8 + gID;
            uint32_t b0 = *(const uint32_t*)(Wsm + n * 264 + d0 + 2 * tig);
            uint32_t b1 = *(const uint32_t*)(Wsm + n * 264 + d0 + 2 * tig + 8);
            float* o = acc + nt * 4;
            asm volatile(
                "mma.sync.aligned.m16n8k16.row.col.f32.f16.f16.f32 "
                "{%0,%1,%2,%3}, {%4,%5,%6,%7}, {%8,%9}, {%0,%1,%2,%3};"
                : "+f"(o[0]), "+f"(o[1]), "+f"(o[2]), "+f"(o[3])
                : "r"(a0), "r"(a1), "r"(a2), "r"(a3), "r"(b0), "r"(b1));
        }
    }

    int r0g = row0 + wr + gID, r1g = r0g + 8;
#pragma unroll
    for (int nt = 0; nt < 4; ++nt) {
        float* o = acc + nt * 4;
        int cc = c0 + wc + nt * 8 + 2 * tig;
        float b0v = bo[cc], b1v = bo[cc + 1];
        float2 x0 = *(const float2*)(x + (size_t)r0g * CDIM + cc);
        float2 x1 = *(const float2*)(x + (size_t)r1g * CDIM + cc);
        float2 v0 = make_float2(x0.x + relu(o[0] + b0v), x0.y + relu(o[1] + b1v));
        float2 v1 = make_float2(x1.x + relu(o[2] + b0v), x1.y + relu(o[3] + b1v));
        *(float2*)(out + (size_t)r0g * CDIM + cc) = v0;
        *(float2*)(out + (size_t)r1g * CDIM + cc) = v1;
    }
}

// ---------------------------------------------------------------------------
extern "C" void kernel_launch(void* const* d_in, const int* in_sizes, int n_in,
                              void* d_out, int out_size)
{
    const float* x  = (const float*)d_in[0];
    const float* Wq = (const float*)d_in[1];
    const float* bq = (const float*)d_in[2];
    const float* Wk = (const float*)d_in[3];
    const float* bk = (const float*)d_in[4];
    const float* Wv = (const float*)d_in[5];
    const float* bv = (const float*)d_in[6];
    const float* Wo = (const float*)d_in[7];
    const float* bo = (const float*)d_in[8];
    float* out = (float*)d_out;

    cudaFuncSetAttribute(attn_kernel, cudaFuncAttributeMaxDynamicSharedMemorySize,
                         ATTN_SMEM_BYTES);
    cudaFuncSetAttribute(qkv_kernel, cudaFuncAttributeMaxDynamicSharedMemorySize,
                         PROJ_SMEM_BYTES);
    cudaFuncSetAttribute(out_kernel, cudaFuncAttributeMaxDynamicSharedMemorySize,
                         PROJ_SMEM_BYTES);

    prep_kernel<<<256, 256>>>(Wq, Wk, Wv, Wo);
    qkv_kernel<<<dim3(256, 5), 256, PROJ_SMEM_BYTES>>>(x, bq, bk, bv);
    attn_kernel<<<dim3(64, 4), 256, ATTN_SMEM_BYTES>>>();
    out_kernel<<<dim3(256, 4), 256, PROJ_SMEM_BYTES>>>(x, bo, out);
}